// round 12
// baseline (speedup 1.0000x reference)
#include <cuda_runtime.h>
#include <cuda_fp16.h>
#include <math.h>

// Problem constants
#define B_  2
#define T_  2048
#define D_  2048
#define E_  3072          // D + 2*KV_DIM
#define KV_ 512
#define HD_ 64
#define NH_ 32
#define BT_ 4096          // B*T

#define LOG2E 1.4426950408889634f

// Scratch (static __device__ arrays; allocation-free rule)
__device__ __half g_xh[BT_ * D_];                       // x hi (left operand only)
__device__ __half g_qkvh[BT_ * E_], g_qkvl[BT_ * E_];   // roped qkv hi/lo
__device__ __half g_ath[BT_ * D_];                      // attn out hi (left only)
__device__ __half g_wqkv_h[E_ * D_], g_wqkv_l[E_ * D_];
__device__ __half g_wout_h[D_ * D_], g_wout_l[D_ * D_];

// ---------------------------------------------------------------------------
// helpers (fp16 split)
// ---------------------------------------------------------------------------
__device__ __forceinline__ unsigned pack2(float x, float y) {
    __half2 h = __floats2half2_rn(x, y);   // .x in low half
    return *(unsigned*)&h;
}
__device__ __forceinline__ float resid(float x) {
    return x - __half2float(__float2half_rn(x));
}
__device__ __forceinline__ void mma16816(float c[4], const unsigned a[4], const unsigned b[2]) {
    asm volatile(
        "mma.sync.aligned.m16n8k16.row.col.f32.f16.f16.f32 "
        "{%0,%1,%2,%3},{%4,%5,%6,%7},{%8,%9},{%0,%1,%2,%3};\n"
        : "+f"(c[0]), "+f"(c[1]), "+f"(c[2]), "+f"(c[3])
        : "r"(a[0]), "r"(a[1]), "r"(a[2]), "r"(a[3]), "r"(b[0]), "r"(b[1]));
}
__device__ __forceinline__ void cp16(void* dst_smem, const void* src) {
    unsigned d = (unsigned)__cvta_generic_to_shared(dst_smem);
    asm volatile("cp.async.cg.shared.global [%0], [%1], 16;\n" :: "r"(d), "l"(src));
}
__device__ __forceinline__ void cp_commit() { asm volatile("cp.async.commit_group;\n" ::: "memory"); }
__device__ __forceinline__ void cp_wait0()  { asm volatile("cp.async.wait_group 0;\n" ::: "memory"); }
__device__ __forceinline__ void cp_wait1()  { asm volatile("cp.async.wait_group 1;\n" ::: "memory"); }
__device__ __forceinline__ void cp_wait2()  { asm volatile("cp.async.wait_group 2;\n" ::: "memory"); }
__device__ __forceinline__ void ldmx4(unsigned r[4], const void* p) {
    unsigned a = (unsigned)__cvta_generic_to_shared(p);
    asm volatile("ldmatrix.sync.aligned.m8n8.x4.shared.b16 {%0,%1,%2,%3},[%4];\n"
                 : "=r"(r[0]), "=r"(r[1]), "=r"(r[2]), "=r"(r[3]) : "r"(a));
}
__device__ __forceinline__ void ldmx4t(unsigned r[4], const void* p) {
    unsigned a = (unsigned)__cvta_generic_to_shared(p);
    asm volatile("ldmatrix.sync.aligned.m8n8.x4.trans.shared.b16 {%0,%1,%2,%3},[%4];\n"
                 : "=r"(r[0]), "=r"(r[1]), "=r"(r[2]), "=r"(r[3]) : "r"(a));
}

// ---------------------------------------------------------------------------
// x split: fp32 -> fp16 hi (x is only ever a LEFT operand; lo never used)
// ---------------------------------------------------------------------------
__global__ void xsplit_kernel(const float* __restrict__ X, __half* __restrict__ Xh)
{
    long i = (long)(blockIdx.x * blockDim.x + threadIdx.x) * 4;
    if (i >= (long)BT_ * D_) return;
    float4 v = *(const float4*)(X + i);
    *(uint2*)(Xh + i) = make_uint2(pack2(v.x, v.y), pack2(v.z, v.w));
}

// ---------------------------------------------------------------------------
// Weight split+transpose: W[K][N] fp32 -> Wt_hi/Wt_lo [N][K] fp16
// ---------------------------------------------------------------------------
__global__ void wsplit_kernel(const float* __restrict__ W,
                              __half* __restrict__ Oh,
                              __half* __restrict__ Ol, int K, int N)
{
    __shared__ float t[32][33];
    int n0 = blockIdx.x * 32, k0 = blockIdx.y * 32;
    for (int i = threadIdx.y; i < 32; i += 8)
        t[i][threadIdx.x] = W[(long)(k0 + i) * N + n0 + threadIdx.x];
    __syncthreads();
    for (int i = threadIdx.y; i < 32; i += 8) {
        float v = t[threadIdx.x][i];
        long o = (long)(n0 + i) * K + k0 + threadIdx.x;
        __half h = __float2half_rn(v);
        Oh[o] = h;
        Ol[o] = __float2half_rn(v - __half2float(h));
    }
}

// ---------------------------------------------------------------------------
// GEMM (fp16x2, mma.sync): C[M,N] = A[M,K] * W[K,N]
// A hi-only [M][K]; W hi/lo transposed [N][K]. Per product: Ah*Bh + Ah*Bl.
// 128x128x32 tiles, 256 threads, warptile 32x64, XOR-swizzled rows,
// 4-stage cp.async ring @ 24 KB/stage -> 96 KB -> 2 CTAs/SM.
// MMA issue order interleaves hi/lo terms of different accumulators so
// no two consecutive mmas share an accumulator (RAW distance 4).
// mode 0: write C fp32.  mode 1: fused RoPE + fp16 hi/lo split -> Ch/Cl.
// ---------------------------------------------------------------------------
#define GMAT 8192                 // bytes per matrix tile (128 rows x 64 B)
#define GSTAGE (3 * GMAT)         // Ah,Bh,Bl = 24576 B
#define GEMM_SMEM (4 * GSTAGE)    // 98304 B

__global__ void __launch_bounds__(256, 2) gemm_fp16x2(
    const __half* __restrict__ Ah_g,
    const __half* __restrict__ Bh_g, const __half* __restrict__ Bl_g,
    float* __restrict__ C, int M, int N, int K, int mode,
    const float* __restrict__ sinb, const float* __restrict__ cosb,
    __half* __restrict__ Ch, __half* __restrict__ Cl)
{
    extern __shared__ __align__(128) char gsm[];
    const int tid = threadIdx.x, lane = tid & 31, warp = tid >> 5;
    const int row0 = blockIdx.y * 128, col0 = blockIdx.x * 128;
    const int m0 = (warp >> 1) * 32, n0w = (warp & 1) * 64;
    const int rw = lane >> 2, cw = lane & 3;
    const int nk = K >> 5;

    float acc[2][8][4];
#pragma unroll
    for (int mt = 0; mt < 2; mt++)
#pragma unroll
        for (int nt = 0; nt < 8; nt++)
#pragma unroll
            for (int e = 0; e < 4; e++) acc[mt][nt][e] = 0.f;

    auto issue = [&](int st, int kb) {
        char* base = gsm + st * GSTAGE;
#pragma unroll
        for (int l = 0; l < 6; l++) {
            int idx = tid + l * 256;               // 0..1535
            int mat = idx >> 9;                    // 0:Ah 1:Bh 2:Bl
            int r   = (idx >> 2) & 127;
            int c   = idx & 3;                     // logical 16B chunk
            const __half* g = (mat == 0) ? Ah_g : (mat == 1) ? Bh_g : Bl_g;
            long grow = (long)((mat == 0 ? row0 : col0) + r);
            cp16(base + mat * GMAT + r * 64 + ((c ^ ((r >> 1) & 3)) << 4),
                 g + grow * K + kb * 32 + c * 8);
        }
        cp_commit();
    };

    issue(0, 0);
    if (nk > 1) issue(1, 1);
    if (nk > 2) issue(2, 2);

    for (int kb = 0; kb < nk; kb++) {
        const int st = kb & 3;
        if (kb + 2 < nk)      cp_wait2();
        else if (kb + 1 < nk) cp_wait1();
        else                  cp_wait0();
        __syncthreads();
        if (kb + 3 < nk) issue((kb + 3) & 3, kb + 3);   // stage freed at iter kb-1

        char* base = gsm + st * GSTAGE;
#pragma unroll
        for (int s = 0; s < 2; s++) {
            unsigned ah[2][4];
#pragma unroll
            for (int mt = 0; mt < 2; mt++) {
                int row = m0 + mt * 16 + (lane & 15);
                int ch  = 2 * s + (lane >> 4);
                ldmx4(ah[mt], base + row * 64 + ((ch ^ ((row >> 1) & 3)) << 4));
            }
#pragma unroll
            for (int ntp = 0; ntp < 4; ntp++) {
                int row = n0w + ntp * 16 + ((lane >> 4) << 3) + (lane & 7);
                int ch  = 2 * s + ((lane & 8) >> 3);
                int off = row * 64 + ((ch ^ ((row >> 1) & 3)) << 4);
                unsigned bh4[4], bl4[4];
                ldmx4(bh4, base + GMAT + off);
                ldmx4(bl4, base + 2 * GMAT + off);
                unsigned bh0[2] = { bh4[0], bh4[1] }, bl0[2] = { bl4[0], bl4[1] };
                unsigned bh1[2] = { bh4[2], bh4[3] }, bl1[2] = { bl4[2], bl4[3] };
                // hi terms for all 4 accumulators, then lo terms: RAW distance 4
                mma16816(acc[0][2 * ntp],     ah[0], bh0);
                mma16816(acc[1][2 * ntp],     ah[1], bh0);
                mma16816(acc[0][2 * ntp + 1], ah[0], bh1);
                mma16816(acc[1][2 * ntp + 1], ah[1], bh1);
                mma16816(acc[0][2 * ntp],     ah[0], bl0);
                mma16816(acc[1][2 * ntp],     ah[1], bl0);
                mma16816(acc[0][2 * ntp + 1], ah[0], bl1);
                mma16816(acc[1][2 * ntp + 1], ah[1], bl1);
            }
        }
    }

    // ---- epilogue
    if (mode == 0) {
#pragma unroll
        for (int mt = 0; mt < 2; mt++) {
#pragma unroll
            for (int nt = 0; nt < 8; nt++) {
                int row = row0 + m0 + mt * 16 + rw;
                int col = col0 + n0w + nt * 8 + cw * 2;
                *(float2*)(C + (long)row * N + col)       = make_float2(acc[mt][nt][0], acc[mt][nt][1]);
                *(float2*)(C + (long)(row + 8) * N + col) = make_float2(acc[mt][nt][2], acc[mt][nt][3]);
            }
        }
    } else {
        const bool isv = (col0 + n0w) >= (D_ + KV_);
#pragma unroll
        for (int mt = 0; mt < 2; mt++) {
            int rbase = row0 + m0 + mt * 16 + rw;
#pragma unroll
            for (int half = 0; half < 2; half++) {
                int r = rbase + half * 8;
                int t = r & (T_ - 1);
                if (!isv) {
#pragma unroll
                    for (int nt = 0; nt < 4; nt++) {
                        float ol0[2], ol1[2];
#pragma unroll
                        for (int d = 0; d < 2; d++) {
                            int e = half * 2 + d;
                            float u1 = acc[mt][nt][e];
                            float u2 = acc[mt][nt + 4][e];
                            int i = nt * 8 + cw * 2 + d;
                            float c1 = cosb[t * HD_ + i],      s1 = sinb[t * HD_ + i];
                            float c2 = cosb[t * HD_ + i + 32], s2 = sinb[t * HD_ + i + 32];
                            ol0[d] = u1 * c1 - u2 * s1;
                            ol1[d] = u2 * c2 + u1 * s2;
                        }
                        long p = (long)r * E_ + col0 + n0w + nt * 8 + cw * 2;
                        *(unsigned*)(Ch + p)      = pack2(ol0[0], ol0[1]);
                        *(unsigned*)(Cl + p)      = pack2(resid(ol0[0]), resid(ol0[1]));
                        *(unsigned*)(Ch + p + 32) = pack2(ol1[0], ol1[1]);
                        *(unsigned*)(Cl + p + 32) = pack2(resid(ol1[0]), resid(ol1[1]));
                    }
                } else {
#pragma unroll
                    for (int nt = 0; nt < 8; nt++) {
                        float v0 = acc[mt][nt][half * 2];
                        float v1 = acc[mt][nt][half * 2 + 1];
                        long p = (long)r * E_ + col0 + n0w + nt * 8 + cw * 2;
                        *(unsigned*)(Ch + p) = pack2(v0, v1);
                        *(unsigned*)(Cl + p) = pack2(resid(v0), resid(v1));
                    }
                }
            }
        }
    }
}

// ---------------------------------------------------------------------------
// Flash attention (causal, GQA), mma.sync fp16x2. 256 threads (8 warps),
// q-tile 128 rows (16/warp). K/V tiles 64 rows, double-buffered cp.async.
// Q hi-only (left); K,V hi+lo (right); P hi-only. MMA hi/lo interleaved
// across n-tiles (RAW distance 2). Largest-first qb scheduling.
// Smem: Q 16 KB + 2 stages x 32 KB = 80 KB -> 2 CTAs/SM.
// ---------------------------------------------------------------------------
#define AMAT_Q 16384              // 128 rows x 128 B
#define AMAT_KV 8192              // 64 rows x 128 B
#define ASTAGE (4 * AMAT_KV)      // Kh,Kl,Vh,Vl = 32768 B
#define ATTN_SMEM (AMAT_Q + 2 * ASTAGE)   // 81920 B

__global__ void __launch_bounds__(256, 2) attn_mma(
    const __half* __restrict__ qkvh, const __half* __restrict__ qkvl,
    __half* __restrict__ oh)
{
    extern __shared__ __align__(128) char asm_[];
    const int tid = threadIdx.x, lane = tid & 31, warp = tid >> 5;
    const int qb = gridDim.x - 1 - blockIdx.x;      // largest-first
    const int h = blockIdx.y, b = blockIdx.z;
    const int q0 = qb * 128;
    const int rw = lane >> 2, cw = lane & 3;
    const int wrow0 = q0 + warp * 16;

    const long qbase = (long)(b * T_) * E_ + h * HD_;
    const long kbase = (long)(b * T_) * E_ + D_ + (h >> 2) * HD_;
    const long vbase = kbase + KV_;

    // issue Q hi (one cp.async group): 128 rows x 8 chunks = 1024
#pragma unroll
    for (int l = 0; l < 4; l++) {
        int idx = tid + l * 256;
        int r = (idx >> 3) & 127, c = idx & 7;
        cp16(asm_ + r * 128 + ((c ^ (r & 7)) << 4),
             qkvh + qbase + (long)(q0 + r) * E_ + c * 8);
    }
    cp_commit();

    const int njb = 2 * qb + 2;

    auto issueKV = [&](int jb, int st) {
        char* sb = asm_ + AMAT_Q + st * ASTAGE;
        const int k0 = jb * 64;
#pragma unroll
        for (int l = 0; l < 8; l++) {
            int idx = tid + l * 256;
            int mat = idx >> 9;                 // 0:Kh 1:Kl 2:Vh 3:Vl
            int r = (idx >> 3) & 63, c = idx & 7;
            const __half* gsrc = (mat & 1) ? qkvl : qkvh;
            long base = (mat >= 2) ? vbase : kbase;
            cp16(sb + mat * AMAT_KV + r * 128 + ((c ^ (r & 7)) << 4),
                 gsrc + base + (long)(k0 + r) * E_ + c * 8);
        }
        cp_commit();
    };

    issueKV(0, 0);
    issueKV(1, 1);

    float O[8][4];
#pragma unroll
    for (int nt = 0; nt < 8; nt++)
#pragma unroll
        for (int e = 0; e < 4; e++) O[nt][e] = 0.f;
    float m0v = -INFINITY, m1v = -INFINITY, l0v = 0.f, l1v = 0.f;

    for (int jb = 0; jb < njb; jb++) {
        const int st = jb & 1;
        const int k0 = jb * 64;
        if (jb + 1 < njb) cp_wait1(); else cp_wait0();
        __syncthreads();

        const bool active = (k0 <= wrow0 + 15);
        if (active) {
            char* sb = asm_ + AMAT_Q + st * ASTAGE;

            // S = Q K^T   (Qh*Kh + Qh*Kl)
            float S[8][4];
#pragma unroll
            for (int nt = 0; nt < 8; nt++)
#pragma unroll
                for (int e = 0; e < 4; e++) S[nt][e] = 0.f;

#pragma unroll
            for (int s = 0; s < 4; s++) {
                unsigned qh4[4];
                {
                    int row = warp * 16 + (lane & 15);
                    int ch  = 2 * s + (lane >> 4);
                    ldmx4(qh4, asm_ + row * 128 + ((ch ^ (row & 7)) << 4));
                }
#pragma unroll
                for (int ntp = 0; ntp < 4; ntp++) {
                    int row = ntp * 16 + ((lane >> 4) << 3) + (lane & 7);
                    int ch  = 2 * s + ((lane & 8) >> 3);
                    int off = row * 128 + ((ch ^ (row & 7)) << 4);
                    unsigned kh4[4], kl4[4];
                    ldmx4(kh4, sb + off);
                    ldmx4(kl4, sb + AMAT_KV + off);
                    unsigned kh0[2] = { kh4[0], kh4[1] }, kl0[2] = { kl4[0], kl4[1] };
                    unsigned kh1[2] = { kh4[2], kh4[3] }, kl1[2] = { kl4[2], kl4[3] };
                    // hi for both n-tiles, then lo: RAW distance 2
                    mma16816(S[2 * ntp],     qh4, kh0);
                    mma16816(S[2 * ntp + 1], qh4, kh1);
                    mma16816(S[2 * ntp],     qh4, kl0);
                    mma16816(S[2 * ntp + 1], qh4, kl1);
                }
            }

            const float sc = 0.125f;
            if (k0 + 63 > wrow0) {      // diagonal tile for this warp
#pragma unroll
                for (int nt = 0; nt < 8; nt++)
#pragma unroll
                    for (int e = 0; e < 4; e++) {
                        int r = wrow0 + rw + ((e >= 2) ? 8 : 0);
                        int c = k0 + nt * 8 + cw * 2 + (e & 1);
                        S[nt][e] = (c <= r) ? S[nt][e] * sc : -1e30f;
                    }
            } else {
#pragma unroll
                for (int nt = 0; nt < 8; nt++)
#pragma unroll
                    for (int e = 0; e < 4; e++) S[nt][e] *= sc;
            }

            // online softmax
            float mx0 = -INFINITY, mx1 = -INFINITY;
#pragma unroll
            for (int nt = 0; nt < 8; nt++) {
                mx0 = fmaxf(mx0, fmaxf(S[nt][0], S[nt][1]));
                mx1 = fmaxf(mx1, fmaxf(S[nt][2], S[nt][3]));
            }
            mx0 = fmaxf(mx0, __shfl_xor_sync(0xffffffff, mx0, 1));
            mx0 = fmaxf(mx0, __shfl_xor_sync(0xffffffff, mx0, 2));
            mx1 = fmaxf(mx1, __shfl_xor_sync(0xffffffff, mx1, 1));
            mx1 = fmaxf(mx1, __shfl_xor_sync(0xffffffff, mx1, 2));
            float mn0 = fmaxf(m0v, mx0), mn1 = fmaxf(m1v, mx1);
            float a0 = exp2f((m0v - mn0) * LOG2E), a1 = exp2f((m1v - mn1) * LOG2E);
            m0v = mn0; m1v = mn1;
            float sum0 = 0.f, sum1 = 0.f;
#pragma unroll
            for (int nt = 0; nt < 8; nt++) {
                float p0 = exp2f((S[nt][0] - mn0) * LOG2E);
                float p1 = exp2f((S[nt][1] - mn0) * LOG2E);
                float p2 = exp2f((S[nt][2] - mn1) * LOG2E);
                float p3 = exp2f((S[nt][3] - mn1) * LOG2E);
                S[nt][0] = p0; S[nt][1] = p1; S[nt][2] = p2; S[nt][3] = p3;
                sum0 += p0 + p1; sum1 += p2 + p3;
            }
            sum0 += __shfl_xor_sync(0xffffffff, sum0, 1);
            sum0 += __shfl_xor_sync(0xffffffff, sum0, 2);
            sum1 += __shfl_xor_sync(0xffffffff, sum1, 1);
            sum1 += __shfl_xor_sync(0xffffffff, sum1, 2);
            l0v = l0v * a0 + sum0;
            l1v = l1v * a1 + sum1;
#pragma unroll
            for (int nt = 0; nt < 8; nt++) {
                O[nt][0] *= a0; O[nt][1] *= a0;
                O[nt][2] *= a1; O[nt][3] *= a1;
            }

            // O += P V   (Ph*Vh + Ph*Vl)
#pragma unroll
            for (int s = 0; s < 4; s++) {
                const int j0 = 2 * s, j1 = 2 * s + 1;
                unsigned ph_[4];
                ph_[0] = pack2(S[j0][0], S[j0][1]);
                ph_[1] = pack2(S[j0][2], S[j0][3]);
                ph_[2] = pack2(S[j1][0], S[j1][1]);
                ph_[3] = pack2(S[j1][2], S[j1][3]);
#pragma unroll
                for (int dt = 0; dt < 4; dt++) {
                    int vrow = s * 16 + (lane & 15);
                    int ch   = 2 * dt + (lane >> 4);
                    int off  = vrow * 128 + ((ch ^ (vrow & 7)) << 4);
                    unsigned vh4[4], vl4[4];
                    ldmx4t(vh4, sb + 2 * AMAT_KV + off);
                    ldmx4t(vl4, sb + 3 * AMAT_KV + off);
                    unsigned bh0[2] = { vh4[0], vh4[1] }, bl0[2] = { vl4[0], vl4[1] };
                    unsigned bh1[2] = { vh4[2], vh4[3] }, bl1[2] = { vl4[2], vl4[3] };
                    // hi for both d-tiles, then lo: RAW distance 2
                    mma16816(O[2 * dt],     ph_, bh0);
                    mma16816(O[2 * dt + 1], ph_, bh1);
                    mma16816(O[2 * dt],     ph_, bl0);
                    mma16816(O[2 * dt + 1], ph_, bl1);
                }
            }
        }
        __syncthreads();
        if (jb + 2 < njb) issueKV(jb + 2, st);
    }

    // epilogue: normalize, write fp16 hi only (attn out is a LEFT operand)
    float i0 = 1.f / l0v, i1 = 1.f / l1v;
    long row = (long)(b * T_ + wrow0 + rw);
    long colb = h * HD_ + cw * 2;
#pragma unroll
    for (int nt = 0; nt < 8; nt++) {
        long p0 = row * D_ + colb + nt * 8;
        long p1 = (row + 8) * D_ + colb + nt * 8;
        *(unsigned*)(oh + p0) = pack2(O[nt][0] * i0, O[nt][1] * i0);
        *(unsigned*)(oh + p1) = pack2(O[nt][2] * i1, O[nt][3] * i1);
    }
}

// ---------------------------------------------------------------------------
// Launch
// ---------------------------------------------------------------------------
extern "C" void kernel_launch(void* const* d_in, const int* in_sizes, int n_in,
                              void* d_out, int out_size)
{
    const float* x     = (const float*)d_in[0];
    const float* sinb  = (const float*)d_in[1];
    const float* cosb  = (const float*)d_in[2];
    const float* w_qkv = (const float*)d_in[3];
    const float* w_out = (const float*)d_in[4];
    float* out = (float*)d_out;

    __half *xh, *qh, *ql, *ath, *wqh, *wql, *woh, *wol;
    cudaGetSymbolAddress((void**)&xh, g_xh);
    cudaGetSymbolAddress((void**)&qh, g_qkvh);
    cudaGetSymbolAddress((void**)&ql, g_qkvl);
    cudaGetSymbolAddress((void**)&ath, g_ath);
    cudaGetSymbolAddress((void**)&wqh, g_wqkv_h);
    cudaGetSymbolAddress((void**)&wql, g_wqkv_l);
    cudaGetSymbolAddress((void**)&woh, g_wout_h);
    cudaGetSymbolAddress((void**)&wol, g_wout_l);

    cudaFuncSetAttribute(gemm_fp16x2, cudaFuncAttributeMaxDynamicSharedMemorySize, GEMM_SMEM);
    cudaFuncSetAttribute(attn_mma, cudaFuncAttributeMaxDynamicSharedMemorySize, ATTN_SMEM);

    // 0) splits
    xsplit_kernel<<<(BT_ * D_ / 4 + 255) / 256, 256>>>(x, xh);
    wsplit_kernel<<<dim3(E_ / 32, D_ / 32), dim3(32, 8)>>>(w_qkv, wqh, wql, D_, E_);
    wsplit_kernel<<<dim3(D_ / 32, D_ / 32), dim3(32, 8)>>>(w_out, woh, wol, D_, D_);

    // 1) QKV projection with fused RoPE + split epilogue
    gemm_fp16x2<<<dim3(E_ / 128, BT_ / 128), 256, GEMM_SMEM>>>(
        xh, wqh, wql, nullptr, BT_, E_, D_, 1, sinb, cosb, qh, ql);

    // 2) Flash attention (q-tile 128, largest-first)
    attn_mma<<<dim3(T_ / 128, NH_, B_), 256, ATTN_SMEM>>>(qh, ql, ath);

    // 3) Output projection (fp32 epilogue)
    gemm_fp16x2<<<dim3(D_ / 128, BT_ / 128), 256, GEMM_SMEM>>>(
        ath, woh, wol, out, BT_, D_, D_, 0, nullptr, nullptr, nullptr, nullptr);
}

// round 13
// speedup vs baseline: 1.1922x; 1.1922x over previous
#include <cuda_runtime.h>
#include <cuda_fp16.h>
#include <math.h>

// Problem constants
#define B_  2
#define T_  2048
#define D_  2048
#define E_  3072          // D + 2*KV_DIM
#define KV_ 512
#define HD_ 64
#define NH_ 32
#define BT_ 4096          // B*T

#define LOG2E 1.4426950408889634f

// Scratch (static __device__ arrays; allocation-free rule)
__device__ __half g_xh[BT_ * D_];                       // x hi
__device__ __half g_qkvh[BT_ * E_];                     // roped qkv hi (only plane)
__device__ __half g_ath[BT_ * D_];                      // attn out hi
__device__ __half g_wqkv_h[E_ * D_];                    // qkv weights hi (single term)
__device__ __half g_wout_h[D_ * D_], g_wout_l[D_ * D_]; // out weights hi/lo (2-term)

// ---------------------------------------------------------------------------
// helpers
// ---------------------------------------------------------------------------
__device__ __forceinline__ unsigned pack2(float x, float y) {
    __half2 h = __floats2half2_rn(x, y);   // .x in low half
    return *(unsigned*)&h;
}
__device__ __forceinline__ float resid(float x) {
    return x - __half2float(__float2half_rn(x));
}
__device__ __forceinline__ void mma16816(float c[4], const unsigned a[4], const unsigned b[2]) {
    asm volatile(
        "mma.sync.aligned.m16n8k16.row.col.f32.f16.f16.f32 "
        "{%0,%1,%2,%3},{%4,%5,%6,%7},{%8,%9},{%0,%1,%2,%3};\n"
        : "+f"(c[0]), "+f"(c[1]), "+f"(c[2]), "+f"(c[3])
        : "r"(a[0]), "r"(a[1]), "r"(a[2]), "r"(a[3]), "r"(b[0]), "r"(b[1]));
}
__device__ __forceinline__ void cp16(void* dst_smem, const void* src) {
    unsigned d = (unsigned)__cvta_generic_to_shared(dst_smem);
    asm volatile("cp.async.cg.shared.global [%0], [%1], 16;\n" :: "r"(d), "l"(src));
}
__device__ __forceinline__ void cp_commit() { asm volatile("cp.async.commit_group;\n" ::: "memory"); }
__device__ __forceinline__ void cp_wait0()  { asm volatile("cp.async.wait_group 0;\n" ::: "memory"); }
__device__ __forceinline__ void cp_wait1()  { asm volatile("cp.async.wait_group 1;\n" ::: "memory"); }
__device__ __forceinline__ void cp_wait2()  { asm volatile("cp.async.wait_group 2;\n" ::: "memory"); }
__device__ __forceinline__ void ldmx4(unsigned r[4], const void* p) {
    unsigned a = (unsigned)__cvta_generic_to_shared(p);
    asm volatile("ldmatrix.sync.aligned.m8n8.x4.shared.b16 {%0,%1,%2,%3},[%4];\n"
                 : "=r"(r[0]), "=r"(r[1]), "=r"(r[2]), "=r"(r[3]) : "r"(a));
}
__device__ __forceinline__ void ldmx4t(unsigned r[4], const void* p) {
    unsigned a = (unsigned)__cvta_generic_to_shared(p);
    asm volatile("ldmatrix.sync.aligned.m8n8.x4.trans.shared.b16 {%0,%1,%2,%3},[%4];\n"
                 : "=r"(r[0]), "=r"(r[1]), "=r"(r[2]), "=r"(r[3]) : "r"(a));
}

// ---------------------------------------------------------------------------
// x split: fp32 -> fp16 hi
// ---------------------------------------------------------------------------
__global__ void xsplit_kernel(const float* __restrict__ X, __half* __restrict__ Xh)
{
    long i = (long)(blockIdx.x * blockDim.x + threadIdx.x) * 4;
    if (i >= (long)BT_ * D_) return;
    float4 v = *(const float4*)(X + i);
    *(uint2*)(Xh + i) = make_uint2(pack2(v.x, v.y), pack2(v.z, v.w));
}

// ---------------------------------------------------------------------------
// Weight transpose: W[K][N] fp32 -> Wt hi (and optional lo) [N][K] fp16
// ---------------------------------------------------------------------------
__global__ void wsplit_kernel(const float* __restrict__ W,
                              __half* __restrict__ Oh,
                              __half* __restrict__ Ol, int K, int N)
{
    __shared__ float t[32][33];
    int n0 = blockIdx.x * 32, k0 = blockIdx.y * 32;
    for (int i = threadIdx.y; i < 32; i += 8)
        t[i][threadIdx.x] = W[(long)(k0 + i) * N + n0 + threadIdx.x];
    __syncthreads();
    for (int i = threadIdx.y; i < 32; i += 8) {
        float v = t[threadIdx.x][i];
        long o = (long)(n0 + i) * K + k0 + threadIdx.x;
        __half h = __float2half_rn(v);
        Oh[o] = h;
        if (Ol) Ol[o] = __float2half_rn(v - __half2float(h));
    }
}

// ---------------------------------------------------------------------------
// GEMM (mma.sync fp16): C[M,N] = A[M,K] * W[K,N]
// A hi [M][K]; W transposed [N][K] hi (+lo when two_term).
// 128x128x32 tiles, 256 threads, warptile 32x64, XOR-swizzled rows,
// 4-stage cp.async ring, 2 CTAs/SM.
// mode 0: write C fp32 (two_term path, out projection).
// mode 1: fused RoPE -> fp16 hi only (single-term path, QKV projection).
// ---------------------------------------------------------------------------
#define GMAT 8192                 // bytes per matrix tile (128 rows x 64 B)
#define GSTAGE (3 * GMAT)         // Ah,Bh,Bl slots = 24576 B
#define GEMM_SMEM (4 * GSTAGE)    // 98304 B

__global__ void __launch_bounds__(256, 2) gemm_fp16(
    const __half* __restrict__ Ah_g,
    const __half* __restrict__ Bh_g, const __half* __restrict__ Bl_g,
    float* __restrict__ C, int M, int N, int K, int mode, int two_term,
    const float* __restrict__ sinb, const float* __restrict__ cosb,
    __half* __restrict__ Ch)
{
    extern __shared__ __align__(128) char gsm[];
    const int tid = threadIdx.x, lane = tid & 31, warp = tid >> 5;
    const int row0 = blockIdx.y * 128, col0 = blockIdx.x * 128;
    const int m0 = (warp >> 1) * 32, n0w = (warp & 1) * 64;
    const int rw = lane >> 2, cw = lane & 3;
    const int nk = K >> 5;

    float acc[2][8][4];
#pragma unroll
    for (int mt = 0; mt < 2; mt++)
#pragma unroll
        for (int nt = 0; nt < 8; nt++)
#pragma unroll
            for (int e = 0; e < 4; e++) acc[mt][nt][e] = 0.f;

    auto issue = [&](int st, int kb) {
        char* base = gsm + st * GSTAGE;
#pragma unroll
        for (int l = 0; l < 6; l++) {
            int idx = tid + l * 256;               // 0..1535
            int mat = idx >> 9;                    // 0:Ah 1:Bh 2:Bl
            if (mat == 2 && !two_term) continue;
            int r   = (idx >> 2) & 127;
            int c   = idx & 3;                     // logical 16B chunk
            const __half* g = (mat == 0) ? Ah_g : (mat == 1) ? Bh_g : Bl_g;
            long grow = (long)((mat == 0 ? row0 : col0) + r);
            cp16(base + mat * GMAT + r * 64 + ((c ^ ((r >> 1) & 3)) << 4),
                 g + grow * K + kb * 32 + c * 8);
        }
        cp_commit();
    };

    issue(0, 0);
    if (nk > 1) issue(1, 1);
    if (nk > 2) issue(2, 2);

    for (int kb = 0; kb < nk; kb++) {
        const int st = kb & 3;
        if (kb + 2 < nk)      cp_wait2();
        else if (kb + 1 < nk) cp_wait1();
        else                  cp_wait0();
        __syncthreads();
        if (kb + 3 < nk) issue((kb + 3) & 3, kb + 3);

        char* base = gsm + st * GSTAGE;
#pragma unroll
        for (int s = 0; s < 2; s++) {
            unsigned ah[2][4];
#pragma unroll
            for (int mt = 0; mt < 2; mt++) {
                int row = m0 + mt * 16 + (lane & 15);
                int ch  = 2 * s + (lane >> 4);
                ldmx4(ah[mt], base + row * 64 + ((ch ^ ((row >> 1) & 3)) << 4));
            }
#pragma unroll
            for (int ntp = 0; ntp < 4; ntp++) {
                int row = n0w + ntp * 16 + ((lane >> 4) << 3) + (lane & 7);
                int ch  = 2 * s + ((lane & 8) >> 3);
                int off = row * 64 + ((ch ^ ((row >> 1) & 3)) << 4);
                unsigned bh4[4];
                ldmx4(bh4, base + GMAT + off);
                unsigned bh0[2] = { bh4[0], bh4[1] }, bh1[2] = { bh4[2], bh4[3] };
                mma16816(acc[0][2 * ntp],     ah[0], bh0);
                mma16816(acc[1][2 * ntp],     ah[1], bh0);
                mma16816(acc[0][2 * ntp + 1], ah[0], bh1);
                mma16816(acc[1][2 * ntp + 1], ah[1], bh1);
                if (two_term) {
                    unsigned bl4[4];
                    ldmx4(bl4, base + 2 * GMAT + off);
                    unsigned bl0[2] = { bl4[0], bl4[1] }, bl1[2] = { bl4[2], bl4[3] };
                    mma16816(acc[0][2 * ntp],     ah[0], bl0);
                    mma16816(acc[1][2 * ntp],     ah[1], bl0);
                    mma16816(acc[0][2 * ntp + 1], ah[0], bl1);
                    mma16816(acc[1][2 * ntp + 1], ah[1], bl1);
                }
            }
        }
    }

    // ---- epilogue
    if (mode == 0) {
#pragma unroll
        for (int mt = 0; mt < 2; mt++) {
#pragma unroll
            for (int nt = 0; nt < 8; nt++) {
                int row = row0 + m0 + mt * 16 + rw;
                int col = col0 + n0w + nt * 8 + cw * 2;
                *(float2*)(C + (long)row * N + col)       = make_float2(acc[mt][nt][0], acc[mt][nt][1]);
                *(float2*)(C + (long)(row + 8) * N + col) = make_float2(acc[mt][nt][2], acc[mt][nt][3]);
            }
        }
    } else {
        const bool isv = (col0 + n0w) >= (D_ + KV_);
#pragma unroll
        for (int mt = 0; mt < 2; mt++) {
            int rbase = row0 + m0 + mt * 16 + rw;
#pragma unroll
            for (int half = 0; half < 2; half++) {
                int r = rbase + half * 8;
                int t = r & (T_ - 1);
                if (!isv) {
#pragma unroll
                    for (int nt = 0; nt < 4; nt++) {
                        float ol0[2], ol1[2];
#pragma unroll
                        for (int d = 0; d < 2; d++) {
                            int e = half * 2 + d;
                            float u1 = acc[mt][nt][e];
                            float u2 = acc[mt][nt + 4][e];
                            int i = nt * 8 + cw * 2 + d;
                            float c1 = cosb[t * HD_ + i],      s1 = sinb[t * HD_ + i];
                            float c2 = cosb[t * HD_ + i + 32], s2 = sinb[t * HD_ + i + 32];
                            ol0[d] = u1 * c1 - u2 * s1;
                            ol1[d] = u2 * c2 + u1 * s2;
                        }
                        long p = (long)r * E_ + col0 + n0w + nt * 8 + cw * 2;
                        *(unsigned*)(Ch + p)      = pack2(ol0[0], ol0[1]);
                        *(unsigned*)(Ch + p + 32) = pack2(ol1[0], ol1[1]);
                    }
                } else {
#pragma unroll
                    for (int nt = 0; nt < 8; nt++) {
                        long p = (long)r * E_ + col0 + n0w + nt * 8 + cw * 2;
                        *(unsigned*)(Ch + p) = pack2(acc[mt][nt][half * 2], acc[mt][nt][half * 2 + 1]);
                    }
                }
            }
        }
    }
}

// ---------------------------------------------------------------------------
// Flash attention (causal, GQA), mma.sync fp16 (hi-only Q,K,V,P).
// 256 threads (8 warps), q-tile 128 rows (16/warp). K/V tiles 64 rows,
// double-buffered cp.async. Largest-first qb scheduling.
// Smem: Q 16 KB + 2 stages x 16 KB = 48 KB -> 2 CTAs/SM.
// ---------------------------------------------------------------------------
#define AMAT_Q 16384              // 128 rows x 128 B
#define AMAT_KV 8192              // 64 rows x 128 B
#define ASTAGE (2 * AMAT_KV)      // Kh,Vh = 16384 B
#define ATTN_SMEM (AMAT_Q + 2 * ASTAGE)   // 49152 B

__global__ void __launch_bounds__(256, 2) attn_mma(
    const __half* __restrict__ qkvh, __half* __restrict__ oh)
{
    extern __shared__ __align__(128) char asm_[];
    const int tid = threadIdx.x, lane = tid & 31, warp = tid >> 5;
    const int qb = gridDim.x - 1 - blockIdx.x;      // largest-first
    const int h = blockIdx.y, b = blockIdx.z;
    const int q0 = qb * 128;
    const int rw = lane >> 2, cw = lane & 3;
    const int wrow0 = q0 + warp * 16;

    const long qbase = (long)(b * T_) * E_ + h * HD_;
    const long kbase = (long)(b * T_) * E_ + D_ + (h >> 2) * HD_;
    const long vbase = kbase + KV_;

    // issue Q hi (one cp.async group): 128 rows x 8 chunks = 1024
#pragma unroll
    for (int l = 0; l < 4; l++) {
        int idx = tid + l * 256;
        int r = (idx >> 3) & 127, c = idx & 7;
        cp16(asm_ + r * 128 + ((c ^ (r & 7)) << 4),
             qkvh + qbase + (long)(q0 + r) * E_ + c * 8);
    }
    cp_commit();

    const int njb = 2 * qb + 2;

    auto issueKV = [&](int jb, int st) {
        char* sb = asm_ + AMAT_Q + st * ASTAGE;
        const int k0 = jb * 64;
#pragma unroll
        for (int l = 0; l < 4; l++) {
            int idx = tid + l * 256;            // 0..1023
            int mat = idx >> 9;                 // 0:Kh 1:Vh
            int r = (idx >> 3) & 63, c = idx & 7;
            long base = mat ? vbase : kbase;
            cp16(sb + mat * AMAT_KV + r * 128 + ((c ^ (r & 7)) << 4),
                 qkvh + base + (long)(k0 + r) * E_ + c * 8);
        }
        cp_commit();
    };

    issueKV(0, 0);
    issueKV(1, 1);

    float O[8][4];
#pragma unroll
    for (int nt = 0; nt < 8; nt++)
#pragma unroll
        for (int e = 0; e < 4; e++) O[nt][e] = 0.f;
    float m0v = -INFINITY, m1v = -INFINITY, l0v = 0.f, l1v = 0.f;

    for (int jb = 0; jb < njb; jb++) {
        const int st = jb & 1;
        const int k0 = jb * 64;
        if (jb + 1 < njb) cp_wait1(); else cp_wait0();
        __syncthreads();

        const bool active = (k0 <= wrow0 + 15);
        if (active) {
            char* sb = asm_ + AMAT_Q + st * ASTAGE;

            // S = Qh Kh^T
            float S[8][4];
#pragma unroll
            for (int nt = 0; nt < 8; nt++)
#pragma unroll
                for (int e = 0; e < 4; e++) S[nt][e] = 0.f;

#pragma unroll
            for (int s = 0; s < 4; s++) {
                unsigned qh4[4];
                {
                    int row = warp * 16 + (lane & 15);
                    int ch  = 2 * s + (lane >> 4);
                    ldmx4(qh4, asm_ + row * 128 + ((ch ^ (row & 7)) << 4));
                }
#pragma unroll
                for (int ntp = 0; ntp < 4; ntp++) {
                    int row = ntp * 16 + ((lane >> 4) << 3) + (lane & 7);
                    int ch  = 2 * s + ((lane & 8) >> 3);
                    int off = row * 128 + ((ch ^ (row & 7)) << 4);
                    unsigned kh4[4];
                    ldmx4(kh4, sb + off);
                    unsigned kh0[2] = { kh4[0], kh4[1] }, kh1[2] = { kh4[2], kh4[3] };
                    mma16816(S[2 * ntp],     qh4, kh0);
                    mma16816(S[2 * ntp + 1], qh4, kh1);
                }
            }

            const float sc = 0.125f;
            if (k0 + 63 > wrow0) {      // diagonal tile for this warp
#pragma unroll
                for (int nt = 0; nt < 8; nt++)
#pragma unroll
                    for (int e = 0; e < 4; e++) {
                        int r = wrow0 + rw + ((e >= 2) ? 8 : 0);
                        int c = k0 + nt * 8 + cw * 2 + (e & 1);
                        S[nt][e] = (c <= r) ? S[nt][e] * sc : -1e30f;
                    }
            } else {
#pragma unroll
                for (int nt = 0; nt < 8; nt++)
#pragma unroll
                    for (int e = 0; e < 4; e++) S[nt][e] *= sc;
            }

            // online softmax
            float mx0 = -INFINITY, mx1 = -INFINITY;
#pragma unroll
            for (int nt = 0; nt < 8; nt++) {
                mx0 = fmaxf(mx0, fmaxf(S[nt][0], S[nt][1]));
                mx1 = fmaxf(mx1, fmaxf(S[nt][2], S[nt][3]));
            }
            mx0 = fmaxf(mx0, __shfl_xor_sync(0xffffffff, mx0, 1));
            mx0 = fmaxf(mx0, __shfl_xor_sync(0xffffffff, mx0, 2));
            mx1 = fmaxf(mx1, __shfl_xor_sync(0xffffffff, mx1, 1));
            mx1 = fmaxf(mx1, __shfl_xor_sync(0xffffffff, mx1, 2));
            float mn0 = fmaxf(m0v, mx0), mn1 = fmaxf(m1v, mx1);
            float a0 = exp2f((m0v - mn0) * LOG2E), a1 = exp2f((m1v - mn1) * LOG2E);
            m0v = mn0; m1v = mn1;
            float sum0 = 0.f, sum1 = 0.f;
#pragma unroll
            for (int nt = 0; nt < 8; nt++) {
                float p0 = exp2f((S[nt][0] - mn0) * LOG2E);
                float p1 = exp2f((S[nt][1] - mn0) * LOG2E);
                float p2 = exp2f((S[nt][2] - mn1) * LOG2E);
                float p3 = exp2f((S[nt][3] - mn1) * LOG2E);
                S[nt][0] = p0; S[nt][1] = p1; S[nt][2] = p2; S[nt][3] = p3;
                sum0 += p0 + p1; sum1 += p2 + p3;
            }
            sum0 += __shfl_xor_sync(0xffffffff, sum0, 1);
            sum0 += __shfl_xor_sync(0xffffffff, sum0, 2);
            sum1 += __shfl_xor_sync(0xffffffff, sum1, 1);
            sum1 += __shfl_xor_sync(0xffffffff, sum1, 2);
            l0v = l0v * a0 + sum0;
            l1v = l1v * a1 + sum1;
#pragma unroll
            for (int nt = 0; nt < 8; nt++) {
                O[nt][0] *= a0; O[nt][1] *= a0;
                O[nt][2] *= a1; O[nt][3] *= a1;
            }

            // O += Ph Vh
#pragma unroll
            for (int s = 0; s < 4; s++) {
                const int j0 = 2 * s, j1 = 2 * s + 1;
                unsigned ph_[4];
                ph_[0] = pack2(S[j0][0], S[j0][1]);
                ph_[1] = pack2(S[j0][2], S[j0][3]);
                ph_[2] = pack2(S[j1][0], S[j1][1]);
                ph_[3] = pack2(S[j1][2], S[j1][3]);
#pragma unroll
                for (int dt = 0; dt < 4; dt++) {
                    int vrow = s * 16 + (lane & 15);
                    int ch   = 2 * dt + (lane >> 4);
                    int off  = vrow * 128 + ((ch ^ (vrow & 7)) << 4);
                    unsigned vh4[4];
                    ldmx4t(vh4, sb + AMAT_KV + off);
                    unsigned bh0[2] = { vh4[0], vh4[1] }, bh1[2] = { vh4[2], vh4[3] };
                    mma16816(O[2 * dt],     ph_, bh0);
                    mma16816(O[2 * dt + 1], ph_, bh1);
                }
            }
        }
        __syncthreads();
        if (jb + 2 < njb) issueKV(jb + 2, st);
    }

    // epilogue: normalize, write fp16 hi
    float i0 = 1.f / l0v, i1 = 1.f / l1v;
    long row = (long)(b * T_ + wrow0 + rw);
    long colb = h * HD_ + cw * 2;
#pragma unroll
    for (int nt = 0; nt < 8; nt++) {
        long p0 = row * D_ + colb + nt * 8;
        long p1 = (row + 8) * D_ + colb + nt * 8;
        *(unsigned*)(oh + p0) = pack2(O[nt][0] * i0, O[nt][1] * i0);
        *(unsigned*)(oh + p1) = pack2(O[nt][2] * i1, O[nt][3] * i1);
    }
}

// ---------------------------------------------------------------------------
// Launch
// ---------------------------------------------------------------------------
extern "C" void kernel_launch(void* const* d_in, const int* in_sizes, int n_in,
                              void* d_out, int out_size)
{
    const float* x     = (const float*)d_in[0];
    const float* sinb  = (const float*)d_in[1];
    const float* cosb  = (const float*)d_in[2];
    const float* w_qkv = (const float*)d_in[3];
    const float* w_out = (const float*)d_in[4];
    float* out = (float*)d_out;

    __half *xh, *qh, *ath, *wqh, *woh, *wol;
    cudaGetSymbolAddress((void**)&xh, g_xh);
    cudaGetSymbolAddress((void**)&qh, g_qkvh);
    cudaGetSymbolAddress((void**)&ath, g_ath);
    cudaGetSymbolAddress((void**)&wqh, g_wqkv_h);
    cudaGetSymbolAddress((void**)&woh, g_wout_h);
    cudaGetSymbolAddress((void**)&wol, g_wout_l);

    cudaFuncSetAttribute(gemm_fp16, cudaFuncAttributeMaxDynamicSharedMemorySize, GEMM_SMEM);
    cudaFuncSetAttribute(attn_mma, cudaFuncAttributeMaxDynamicSharedMemorySize, ATTN_SMEM);

    // 0) splits
    xsplit_kernel<<<(BT_ * D_ / 4 + 255) / 256, 256>>>(x, xh);
    wsplit_kernel<<<dim3(E_ / 32, D_ / 32), dim3(32, 8)>>>(w_qkv, wqh, nullptr, D_, E_);
    wsplit_kernel<<<dim3(D_ / 32, D_ / 32), dim3(32, 8)>>>(w_out, woh, wol, D_, D_);

    // 1) QKV projection, single-term, fused RoPE -> fp16 hi
    gemm_fp16<<<dim3(E_ / 128, BT_ / 128), 256, GEMM_SMEM>>>(
        xh, wqh, nullptr, nullptr, BT_, E_, D_, 1, 0, sinb, cosb, qh);

    // 2) Flash attention (q-tile 128, largest-first, hi-only)
    attn_mma<<<dim3(T_ / 128, NH_, B_), 256, ATTN_SMEM>>>(qh, ath);

    // 3) Output projection, two-term, fp32 epilogue
    gemm_fp16<<<dim3(D_ / 128, BT_ / 128), 256, GEMM_SMEM>>>(
        ath, woh, wol, out, BT_, D_, D_, 0, 1, nullptr, nullptr, nullptr);
}

// round 14
// speedup vs baseline: 1.7318x; 1.4526x over previous
#include <cuda_runtime.h>
#include <cuda_fp16.h>
#include <math.h>

// Problem constants
#define B_  2
#define T_  2048
#define D_  2048
#define E_  3072          // D + 2*KV_DIM
#define KV_ 512
#define HD_ 64
#define NH_ 32
#define BT_ 4096          // B*T

#define LOG2E 1.4426950408889634f

// Scratch (static __device__ arrays; allocation-free rule)
__device__ __half g_xh[BT_ * D_];      // x hi
__device__ __half g_qkvh[BT_ * E_];    // roped qkv hi
__device__ __half g_ath[BT_ * D_];     // attn out hi
__device__ __half g_wqkv_h[E_ * D_];   // qkv weights hi
__device__ __half g_wout_h[D_ * D_];   // out weights hi

// ---------------------------------------------------------------------------
// helpers
// ---------------------------------------------------------------------------
__device__ __forceinline__ unsigned pack2(float x, float y) {
    __half2 h = __floats2half2_rn(x, y);   // .x in low half
    return *(unsigned*)&h;
}
__device__ __forceinline__ void mma16816(float c[4], const unsigned a[4], const unsigned b[2]) {
    asm volatile(
        "mma.sync.aligned.m16n8k16.row.col.f32.f16.f16.f32 "
        "{%0,%1,%2,%3},{%4,%5,%6,%7},{%8,%9},{%0,%1,%2,%3};\n"
        : "+f"(c[0]), "+f"(c[1]), "+f"(c[2]), "+f"(c[3])
        : "r"(a[0]), "r"(a[1]), "r"(a[2]), "r"(a[3]), "r"(b[0]), "r"(b[1]));
}
__device__ __forceinline__ void cp16(void* dst_smem, const void* src) {
    unsigned d = (unsigned)__cvta_generic_to_shared(dst_smem);
    asm volatile("cp.async.cg.shared.global [%0], [%1], 16;\n" :: "r"(d), "l"(src));
}
__device__ __forceinline__ void cp_commit() { asm volatile("cp.async.commit_group;\n" ::: "memory"); }
__device__ __forceinline__ void cp_wait0()  { asm volatile("cp.async.wait_group 0;\n" ::: "memory"); }
__device__ __forceinline__ void cp_wait1()  { asm volatile("cp.async.wait_group 1;\n" ::: "memory"); }
__device__ __forceinline__ void ldmx4(unsigned r[4], const void* p) {
    unsigned a = (unsigned)__cvta_generic_to_shared(p);
    asm volatile("ldmatrix.sync.aligned.m8n8.x4.shared.b16 {%0,%1,%2,%3},[%4];\n"
                 : "=r"(r[0]), "=r"(r[1]), "=r"(r[2]), "=r"(r[3]) : "r"(a));
}
__device__ __forceinline__ void ldmx4t(unsigned r[4], const void* p) {
    unsigned a = (unsigned)__cvta_generic_to_shared(p);
    asm volatile("ldmatrix.sync.aligned.m8n8.x4.trans.shared.b16 {%0,%1,%2,%3},[%4];\n"
                 : "=r"(r[0]), "=r"(r[1]), "=r"(r[2]), "=r"(r[3]) : "r"(a));
}

// ---------------------------------------------------------------------------
// x convert: fp32 -> fp16
// ---------------------------------------------------------------------------
__global__ void xsplit_kernel(const float* __restrict__ X, __half* __restrict__ Xh)
{
    long i = (long)(blockIdx.x * blockDim.x + threadIdx.x) * 4;
    if (i >= (long)BT_ * D_) return;
    float4 v = *(const float4*)(X + i);
    *(uint2*)(Xh + i) = make_uint2(pack2(v.x, v.y), pack2(v.z, v.w));
}

// ---------------------------------------------------------------------------
// Weight transpose+convert: W[K][N] fp32 -> Wt [N][K] fp16
// ---------------------------------------------------------------------------
__global__ void wsplit_kernel(const float* __restrict__ W,
                              __half* __restrict__ Oh, int K, int N)
{
    __shared__ float t[32][33];
    int n0 = blockIdx.x * 32, k0 = blockIdx.y * 32;
    for (int i = threadIdx.y; i < 32; i += 8)
        t[i][threadIdx.x] = W[(long)(k0 + i) * N + n0 + threadIdx.x];
    __syncthreads();
    for (int i = threadIdx.y; i < 32; i += 8)
        Oh[(long)(n0 + i) * K + k0 + threadIdx.x] = __float2half_rn(t[threadIdx.x][i]);
}

// ---------------------------------------------------------------------------
// GEMM (mma.sync fp16, single-term): C[M,N] = A[M,K] * W[K,N]
// A [M][K] fp16; W transposed [N][K] fp16.
// 128x128x64 tiles (BK=64), 256 threads, warptile 32x64, 128B XOR-swizzled
// rows, 3-stage cp.async ring @ 32 KB/stage -> 96 KB -> 2 CTAs/SM.
// One __syncthreads per 64-k block (half the barrier count of BK=32).
// mode 0: write C fp32.  mode 1: fused RoPE -> fp16 (QKV projection).
// ---------------------------------------------------------------------------
#define GMAT 16384                // bytes per matrix tile (128 rows x 128 B)
#define GSTAGE (2 * GMAT)         // A,B = 32768 B
#define GEMM_SMEM (3 * GSTAGE)    // 98304 B

__global__ void __launch_bounds__(256, 2) gemm_fp16(
    const __half* __restrict__ Ah_g, const __half* __restrict__ Bh_g,
    float* __restrict__ C, int M, int N, int K, int mode,
    const float* __restrict__ sinb, const float* __restrict__ cosb,
    __half* __restrict__ Ch)
{
    extern __shared__ __align__(128) char gsm[];
    const int tid = threadIdx.x, lane = tid & 31, warp = tid >> 5;
    const int row0 = blockIdx.y * 128, col0 = blockIdx.x * 128;
    const int m0 = (warp >> 1) * 32, n0w = (warp & 1) * 64;
    const int rw = lane >> 2, cw = lane & 3;
    const int nk = K >> 6;

    float acc[2][8][4];
#pragma unroll
    for (int mt = 0; mt < 2; mt++)
#pragma unroll
        for (int nt = 0; nt < 8; nt++)
#pragma unroll
            for (int e = 0; e < 4; e++) acc[mt][nt][e] = 0.f;

    auto issue = [&](int st, int kb) {
        char* base = gsm + st * GSTAGE;
#pragma unroll
        for (int l = 0; l < 8; l++) {
            int idx = tid + l * 256;               // 0..2047
            int mat = idx >> 10;                   // 0:A 1:B
            int r   = (idx >> 3) & 127;
            int c   = idx & 7;                     // logical 16B chunk
            const __half* g = mat ? Bh_g : Ah_g;
            long grow = (long)((mat ? col0 : row0) + r);
            cp16(base + mat * GMAT + r * 128 + ((c ^ (r & 7)) << 4),
                 g + grow * K + kb * 64 + c * 8);
        }
        cp_commit();
    };

    issue(0, 0);
    if (nk > 1) issue(1, 1);

    for (int kb = 0; kb < nk; kb++) {
        const int st = kb % 3;
        if (kb + 1 < nk) cp_wait1(); else cp_wait0();
        __syncthreads();
        if (kb + 2 < nk) issue((kb + 2) % 3, kb + 2);   // stage free since last iter

        char* base = gsm + st * GSTAGE;
#pragma unroll
        for (int s = 0; s < 4; s++) {
            unsigned ah[2][4];
#pragma unroll
            for (int mt = 0; mt < 2; mt++) {
                int row = m0 + mt * 16 + (lane & 15);
                int ch  = 2 * s + (lane >> 4);
                ldmx4(ah[mt], base + row * 128 + ((ch ^ (row & 7)) << 4));
            }
#pragma unroll
            for (int ntp = 0; ntp < 4; ntp++) {
                int row = n0w + ntp * 16 + ((lane >> 4) << 3) + (lane & 7);
                int ch  = 2 * s + ((lane & 8) >> 3);
                unsigned bh4[4];
                ldmx4(bh4, base + GMAT + row * 128 + ((ch ^ (row & 7)) << 4));
                unsigned bh0[2] = { bh4[0], bh4[1] }, bh1[2] = { bh4[2], bh4[3] };
                mma16816(acc[0][2 * ntp],     ah[0], bh0);
                mma16816(acc[1][2 * ntp],     ah[1], bh0);
                mma16816(acc[0][2 * ntp + 1], ah[0], bh1);
                mma16816(acc[1][2 * ntp + 1], ah[1], bh1);
            }
        }
    }

    // ---- epilogue
    if (mode == 0) {
#pragma unroll
        for (int mt = 0; mt < 2; mt++) {
#pragma unroll
            for (int nt = 0; nt < 8; nt++) {
                int row = row0 + m0 + mt * 16 + rw;
                int col = col0 + n0w + nt * 8 + cw * 2;
                *(float2*)(C + (long)row * N + col)       = make_float2(acc[mt][nt][0], acc[mt][nt][1]);
                *(float2*)(C + (long)(row + 8) * N + col) = make_float2(acc[mt][nt][2], acc[mt][nt][3]);
            }
        }
    } else {
        const bool isv = (col0 + n0w) >= (D_ + KV_);
#pragma unroll
        for (int mt = 0; mt < 2; mt++) {
            int rbase = row0 + m0 + mt * 16 + rw;
#pragma unroll
            for (int half = 0; half < 2; half++) {
                int r = rbase + half * 8;
                int t = r & (T_ - 1);
                if (!isv) {
#pragma unroll
                    for (int nt = 0; nt < 4; nt++) {
                        float ol0[2], ol1[2];
#pragma unroll
                        for (int d = 0; d < 2; d++) {
                            int e = half * 2 + d;
                            float u1 = acc[mt][nt][e];
                            float u2 = acc[mt][nt + 4][e];
                            int i = nt * 8 + cw * 2 + d;
                            float c1 = cosb[t * HD_ + i],      s1 = sinb[t * HD_ + i];
                            float c2 = cosb[t * HD_ + i + 32], s2 = sinb[t * HD_ + i + 32];
                            ol0[d] = u1 * c1 - u2 * s1;
                            ol1[d] = u2 * c2 + u1 * s2;
                        }
                        long p = (long)r * E_ + col0 + n0w + nt * 8 + cw * 2;
                        *(unsigned*)(Ch + p)      = pack2(ol0[0], ol0[1]);
                        *(unsigned*)(Ch + p + 32) = pack2(ol1[0], ol1[1]);
                    }
                } else {
#pragma unroll
                    for (int nt = 0; nt < 8; nt++) {
                        long p = (long)r * E_ + col0 + n0w + nt * 8 + cw * 2;
                        *(unsigned*)(Ch + p) = pack2(acc[mt][nt][half * 2], acc[mt][nt][half * 2 + 1]);
                    }
                }
            }
        }
    }
}

// ---------------------------------------------------------------------------
// Flash attention (causal, GQA), mma.sync fp16 (hi-only Q,K,V,P).
// 256 threads (8 warps), q-tile 128 rows (16/warp). K/V tiles 64 rows,
// double-buffered cp.async. Largest-first qb scheduling.
// Smem: Q 16 KB + 2 stages x 16 KB = 48 KB -> 2 CTAs/SM.
// ---------------------------------------------------------------------------
#define AMAT_Q 16384              // 128 rows x 128 B
#define AMAT_KV 8192              // 64 rows x 128 B
#define ASTAGE (2 * AMAT_KV)      // Kh,Vh = 16384 B
#define ATTN_SMEM (AMAT_Q + 2 * ASTAGE)   // 49152 B

__global__ void __launch_bounds__(256, 2) attn_mma(
    const __half* __restrict__ qkvh, __half* __restrict__ oh)
{
    extern __shared__ __align__(128) char asm_[];
    const int tid = threadIdx.x, lane = tid & 31, warp = tid >> 5;
    const int qb = gridDim.x - 1 - blockIdx.x;      // largest-first
    const int h = blockIdx.y, b = blockIdx.z;
    const int q0 = qb * 128;
    const int rw = lane >> 2, cw = lane & 3;
    const int wrow0 = q0 + warp * 16;

    const long qbase = (long)(b * T_) * E_ + h * HD_;
    const long kbase = (long)(b * T_) * E_ + D_ + (h >> 2) * HD_;
    const long vbase = kbase + KV_;

    // issue Q (one cp.async group): 128 rows x 8 chunks = 1024
#pragma unroll
    for (int l = 0; l < 4; l++) {
        int idx = tid + l * 256;
        int r = (idx >> 3) & 127, c = idx & 7;
        cp16(asm_ + r * 128 + ((c ^ (r & 7)) << 4),
             qkvh + qbase + (long)(q0 + r) * E_ + c * 8);
    }
    cp_commit();

    const int njb = 2 * qb + 2;

    auto issueKV = [&](int jb, int st) {
        char* sb = asm_ + AMAT_Q + st * ASTAGE;
        const int k0 = jb * 64;
#pragma unroll
        for (int l = 0; l < 4; l++) {
            int idx = tid + l * 256;            // 0..1023
            int mat = idx >> 9;                 // 0:Kh 1:Vh
            int r = (idx >> 3) & 63, c = idx & 7;
            long base = mat ? vbase : kbase;
            cp16(sb + mat * AMAT_KV + r * 128 + ((c ^ (r & 7)) << 4),
                 qkvh + base + (long)(k0 + r) * E_ + c * 8);
        }
        cp_commit();
    };

    issueKV(0, 0);
    issueKV(1, 1);

    float O[8][4];
#pragma unroll
    for (int nt = 0; nt < 8; nt++)
#pragma unroll
        for (int e = 0; e < 4; e++) O[nt][e] = 0.f;
    float m0v = -INFINITY, m1v = -INFINITY, l0v = 0.f, l1v = 0.f;

    for (int jb = 0; jb < njb; jb++) {
        const int st = jb & 1;
        const int k0 = jb * 64;
        if (jb + 1 < njb) cp_wait1(); else cp_wait0();
        __syncthreads();

        const bool active = (k0 <= wrow0 + 15);
        if (active) {
            char* sb = asm_ + AMAT_Q + st * ASTAGE;

            // S = Q K^T
            float S[8][4];
#pragma unroll
            for (int nt = 0; nt < 8; nt++)
#pragma unroll
                for (int e = 0; e < 4; e++) S[nt][e] = 0.f;

#pragma unroll
            for (int s = 0; s < 4; s++) {
                unsigned qh4[4];
                {
                    int row = warp * 16 + (lane & 15);
                    int ch  = 2 * s + (lane >> 4);
                    ldmx4(qh4, asm_ + row * 128 + ((ch ^ (row & 7)) << 4));
                }
#pragma unroll
                for (int ntp = 0; ntp < 4; ntp++) {
                    int row = ntp * 16 + ((lane >> 4) << 3) + (lane & 7);
                    int ch  = 2 * s + ((lane & 8) >> 3);
                    unsigned kh4[4];
                    ldmx4(kh4, sb + row * 128 + ((ch ^ (row & 7)) << 4));
                    unsigned kh0[2] = { kh4[0], kh4[1] }, kh1[2] = { kh4[2], kh4[3] };
                    mma16816(S[2 * ntp],     qh4, kh0);
                    mma16816(S[2 * ntp + 1], qh4, kh1);
                }
            }

            const float sc = 0.125f;
            if (k0 + 63 > wrow0) {      // diagonal tile for this warp
#pragma unroll
                for (int nt = 0; nt < 8; nt++)
#pragma unroll
                    for (int e = 0; e < 4; e++) {
                        int r = wrow0 + rw + ((e >= 2) ? 8 : 0);
                        int c = k0 + nt * 8 + cw * 2 + (e & 1);
                        S[nt][e] = (c <= r) ? S[nt][e] * sc : -1e30f;
                    }
            } else {
#pragma unroll
                for (int nt = 0; nt < 8; nt++)
#pragma unroll
                    for (int e = 0; e < 4; e++) S[nt][e] *= sc;
            }

            // online softmax
            float mx0 = -INFINITY, mx1 = -INFINITY;
#pragma unroll
            for (int nt = 0; nt < 8; nt++) {
                mx0 = fmaxf(mx0, fmaxf(S[nt][0], S[nt][1]));
                mx1 = fmaxf(mx1, fmaxf(S[nt][2], S[nt][3]));
            }
            mx0 = fmaxf(mx0, __shfl_xor_sync(0xffffffff, mx0, 1));
            mx0 = fmaxf(mx0, __shfl_xor_sync(0xffffffff, mx0, 2));
            mx1 = fmaxf(mx1, __shfl_xor_sync(0xffffffff, mx1, 1));
            mx1 = fmaxf(mx1, __shfl_xor_sync(0xffffffff, mx1, 2));
            float mn0 = fmaxf(m0v, mx0), mn1 = fmaxf(m1v, mx1);
            float a0 = exp2f((m0v - mn0) * LOG2E), a1 = exp2f((m1v - mn1) * LOG2E);
            m0v = mn0; m1v = mn1;
            float sum0 = 0.f, sum1 = 0.f;
#pragma unroll
            for (int nt = 0; nt < 8; nt++) {
                float p0 = exp2f((S[nt][0] - mn0) * LOG2E);
                float p1 = exp2f((S[nt][1] - mn0) * LOG2E);
                float p2 = exp2f((S[nt][2] - mn1) * LOG2E);
                float p3 = exp2f((S[nt][3] - mn1) * LOG2E);
                S[nt][0] = p0; S[nt][1] = p1; S[nt][2] = p2; S[nt][3] = p3;
                sum0 += p0 + p1; sum1 += p2 + p3;
            }
            sum0 += __shfl_xor_sync(0xffffffff, sum0, 1);
            sum0 += __shfl_xor_sync(0xffffffff, sum0, 2);
            sum1 += __shfl_xor_sync(0xffffffff, sum1, 1);
            sum1 += __shfl_xor_sync(0xffffffff, sum1, 2);
            l0v = l0v * a0 + sum0;
            l1v = l1v * a1 + sum1;
#pragma unroll
            for (int nt = 0; nt < 8; nt++) {
                O[nt][0] *= a0; O[nt][1] *= a0;
                O[nt][2] *= a1; O[nt][3] *= a1;
            }

            // O += P V
#pragma unroll
            for (int s = 0; s < 4; s++) {
                const int j0 = 2 * s, j1 = 2 * s + 1;
                unsigned ph_[4];
                ph_[0] = pack2(S[j0][0], S[j0][1]);
                ph_[1] = pack2(S[j0][2], S[j0][3]);
                ph_[2] = pack2(S[j1][0], S[j1][1]);
                ph_[3] = pack2(S[j1][2], S[j1][3]);
#pragma unroll
                for (int dt = 0; dt < 4; dt++) {
                    int vrow = s * 16 + (lane & 15);
                    int ch   = 2 * dt + (lane >> 4);
                    unsigned vh4[4];
                    ldmx4t(vh4, sb + AMAT_KV + vrow * 128 + ((ch ^ (vrow & 7)) << 4));
                    unsigned bh0[2] = { vh4[0], vh4[1] }, bh1[2] = { vh4[2], vh4[3] };
                    mma16816(O[2 * dt],     ph_, bh0);
                    mma16816(O[2 * dt + 1], ph_, bh1);
                }
            }
        }
        __syncthreads();
        if (jb + 2 < njb) issueKV(jb + 2, st);
    }

    // epilogue: normalize, write fp16
    float i0 = 1.f / l0v, i1 = 1.f / l1v;
    long row = (long)(b * T_ + wrow0 + rw);
    long colb = h * HD_ + cw * 2;
#pragma unroll
    for (int nt = 0; nt < 8; nt++) {
        long p0 = row * D_ + colb + nt * 8;
        long p1 = (row + 8) * D_ + colb + nt * 8;
        *(unsigned*)(oh + p0) = pack2(O[nt][0] * i0, O[nt][1] * i0);
        *(unsigned*)(oh + p1) = pack2(O[nt][2] * i1, O[nt][3] * i1);
    }
}

// ---------------------------------------------------------------------------
// Launch
// ---------------------------------------------------------------------------
extern "C" void kernel_launch(void* const* d_in, const int* in_sizes, int n_in,
                              void* d_out, int out_size)
{
    const float* x     = (const float*)d_in[0];
    const float* sinb  = (const float*)d_in[1];
    const float* cosb  = (const float*)d_in[2];
    const float* w_qkv = (const float*)d_in[3];
    const float* w_out = (const float*)d_in[4];
    float* out = (float*)d_out;

    __half *xh, *qh, *ath, *wqh, *woh;
    cudaGetSymbolAddress((void**)&xh, g_xh);
    cudaGetSymbolAddress((void**)&qh, g_qkvh);
    cudaGetSymbolAddress((void**)&ath, g_ath);
    cudaGetSymbolAddress((void**)&wqh, g_wqkv_h);
    cudaGetSymbolAddress((void**)&woh, g_wout_h);

    cudaFuncSetAttribute(gemm_fp16, cudaFuncAttributeMaxDynamicSharedMemorySize, GEMM_SMEM);
    cudaFuncSetAttribute(attn_mma, cudaFuncAttributeMaxDynamicSharedMemorySize, ATTN_SMEM);

    // 0) converts
    xsplit_kernel<<<(BT_ * D_ / 4 + 255) / 256, 256>>>(x, xh);
    wsplit_kernel<<<dim3(E_ / 32, D_ / 32), dim3(32, 8)>>>(w_qkv, wqh, D_, E_);
    wsplit_kernel<<<dim3(D_ / 32, D_ / 32), dim3(32, 8)>>>(w_out, woh, D_, D_);

    // 1) QKV projection, fused RoPE -> fp16
    gemm_fp16<<<dim3(E_ / 128, BT_ / 128), 256, GEMM_SMEM>>>(
        xh, wqh, nullptr, BT_, E_, D_, 1, sinb, cosb, qh);

    // 2) Flash attention (q-tile 128, largest-first)
    attn_mma<<<dim3(T_ / 128, NH_, B_), 256, ATTN_SMEM>>>(qh, ath);

    // 3) Output projection, fp32 epilogue
    gemm_fp16<<<dim3(D_ / 128, BT_ / 128), 256, GEMM_SMEM>>>(
        ath, woh, out, BT_, D_, D_, 0, nullptr, nullptr, nullptr);
}

// round 15
// speedup vs baseline: 1.7528x; 1.0121x over previous
#include <cuda_runtime.h>
#include <cuda_fp16.h>
#include <math.h>

// Problem constants
#define B_  2
#define T_  2048
#define D_  2048
#define E_  3072          // D + 2*KV_DIM
#define KV_ 512
#define HD_ 64
#define NH_ 32
#define BT_ 4096          // B*T

#define LOG2E 1.4426950408889634f

// Scratch (static __device__ arrays; allocation-free rule)
__device__ __half g_xh[BT_ * D_];      // x hi
__device__ __half g_qkvh[BT_ * E_];    // roped qkv hi
__device__ __half g_ath[BT_ * D_];     // attn out hi
__device__ __half g_wqkv_h[E_ * D_];   // qkv weights hi
__device__ __half g_wout_h[D_ * D_];   // out weights hi

// ---------------------------------------------------------------------------
// helpers
// ---------------------------------------------------------------------------
__device__ __forceinline__ unsigned pack2(float x, float y) {
    __half2 h = __floats2half2_rn(x, y);   // .x in low half
    return *(unsigned*)&h;
}
__device__ __forceinline__ void mma16816(float c[4], const unsigned a[4], const unsigned b[2]) {
    asm volatile(
        "mma.sync.aligned.m16n8k16.row.col.f32.f16.f16.f32 "
        "{%0,%1,%2,%3},{%4,%5,%6,%7},{%8,%9},{%0,%1,%2,%3};\n"
        : "+f"(c[0]), "+f"(c[1]), "+f"(c[2]), "+f"(c[3])
        : "r"(a[0]), "r"(a[1]), "r"(a[2]), "r"(a[3]), "r"(b[0]), "r"(b[1]));
}
__device__ __forceinline__ void cp16(void* dst_smem, const void* src) {
    unsigned d = (unsigned)__cvta_generic_to_shared(dst_smem);
    asm volatile("cp.async.cg.shared.global [%0], [%1], 16;\n" :: "r"(d), "l"(src));
}
__device__ __forceinline__ void cp_commit() { asm volatile("cp.async.commit_group;\n" ::: "memory"); }
__device__ __forceinline__ void cp_wait0()  { asm volatile("cp.async.wait_group 0;\n" ::: "memory"); }
__device__ __forceinline__ void cp_wait1()  { asm volatile("cp.async.wait_group 1;\n" ::: "memory"); }
__device__ __forceinline__ void ldmx4(unsigned r[4], const void* p) {
    unsigned a = (unsigned)__cvta_generic_to_shared(p);
    asm volatile("ldmatrix.sync.aligned.m8n8.x4.shared.b16 {%0,%1,%2,%3},[%4];\n"
                 : "=r"(r[0]), "=r"(r[1]), "=r"(r[2]), "=r"(r[3]) : "r"(a));
}
__device__ __forceinline__ void ldmx4t(unsigned r[4], const void* p) {
    unsigned a = (unsigned)__cvta_generic_to_shared(p);
    asm volatile("ldmatrix.sync.aligned.m8n8.x4.trans.shared.b16 {%0,%1,%2,%3},[%4];\n"
                 : "=r"(r[0]), "=r"(r[1]), "=r"(r[2]), "=r"(r[3]) : "r"(a));
}

// ---------------------------------------------------------------------------
// Merged convert kernel. One launch, three jobs (blockIdx.z):
//  z=0: x fp32 -> fp16            (8192 blocks used)
//  z=1: w_qkv transpose+convert   (6144 blocks: 96 n-tiles x 64 k-tiles)
//  z=2: w_out transpose+convert   (4096 blocks: 64 x 64)
// All blocks are 256 threads (32x8 for transpose jobs).
// ---------------------------------------------------------------------------
__global__ void convert_all(const float* __restrict__ X,
                            const float* __restrict__ Wq,
                            const float* __restrict__ Wo,
                            __half* __restrict__ Xh,
                            __half* __restrict__ Oq,
                            __half* __restrict__ Oo)
{
    const int bx = blockIdx.x, z = blockIdx.z;
    if (z == 0) {
        int tid = threadIdx.y * 32 + threadIdx.x;
        long i = ((long)bx * 256 + tid) * 4;
        if (i >= (long)BT_ * D_) return;
        float4 v = *(const float4*)(X + i);
        *(uint2*)(Xh + i) = make_uint2(pack2(v.x, v.y), pack2(v.z, v.w));
        return;
    }
    const float* W = (z == 1) ? Wq : Wo;
    __half* O      = (z == 1) ? Oq : Oo;
    const int N    = (z == 1) ? E_ : D_;
    const int K    = D_;
    const int ntiles = N / 32;
    if (bx >= ntiles * (K / 32)) return;
    int n0 = (bx % ntiles) * 32, k0 = (bx / ntiles) * 32;
    __shared__ float t[32][33];
    for (int i = threadIdx.y; i < 32; i += 8)
        t[i][threadIdx.x] = W[(long)(k0 + i) * N + n0 + threadIdx.x];
    __syncthreads();
    for (int i = threadIdx.y; i < 32; i += 8)
        O[(long)(n0 + i) * K + k0 + threadIdx.x] = __float2half_rn(t[threadIdx.x][i]);
}

// ---------------------------------------------------------------------------
// GEMM (mma.sync fp16, single-term): C[M,N] = A[M,K] * W[K,N]
// A [M][K] fp16; W transposed [N][K] fp16.
// 128x128x64 tiles (BK=64), 256 threads, warptile 32x64, 128B XOR-swizzled
// rows, 3-stage cp.async ring @ 32 KB/stage -> 96 KB -> 2 CTAs/SM.
// mode 0: write C fp32.  mode 1: fused RoPE -> fp16 (QKV projection).
// ---------------------------------------------------------------------------
#define GMAT 16384                // bytes per matrix tile (128 rows x 128 B)
#define GSTAGE (2 * GMAT)         // A,B = 32768 B
#define GEMM_SMEM (3 * GSTAGE)    // 98304 B

__global__ void __launch_bounds__(256, 2) gemm_fp16(
    const __half* __restrict__ Ah_g, const __half* __restrict__ Bh_g,
    float* __restrict__ C, int M, int N, int K, int mode,
    const float* __restrict__ sinb, const float* __restrict__ cosb,
    __half* __restrict__ Ch)
{
    extern __shared__ __align__(128) char gsm[];
    const int tid = threadIdx.x, lane = tid & 31, warp = tid >> 5;
    const int row0 = blockIdx.y * 128, col0 = blockIdx.x * 128;
    const int m0 = (warp >> 1) * 32, n0w = (warp & 1) * 64;
    const int rw = lane >> 2, cw = lane & 3;
    const int nk = K >> 6;

    float acc[2][8][4];
#pragma unroll
    for (int mt = 0; mt < 2; mt++)
#pragma unroll
        for (int nt = 0; nt < 8; nt++)
#pragma unroll
            for (int e = 0; e < 4; e++) acc[mt][nt][e] = 0.f;

    auto issue = [&](int st, int kb) {
        char* base = gsm + st * GSTAGE;
#pragma unroll
        for (int l = 0; l < 8; l++) {
            int idx = tid + l * 256;               // 0..2047
            int mat = idx >> 10;                   // 0:A 1:B
            int r   = (idx >> 3) & 127;
            int c   = idx & 7;                     // logical 16B chunk
            const __half* g = mat ? Bh_g : Ah_g;
            long grow = (long)((mat ? col0 : row0) + r);
            cp16(base + mat * GMAT + r * 128 + ((c ^ (r & 7)) << 4),
                 g + grow * K + kb * 64 + c * 8);
        }
        cp_commit();
    };

    issue(0, 0);
    if (nk > 1) issue(1, 1);

    for (int kb = 0; kb < nk; kb++) {
        const int st = kb % 3;
        if (kb + 1 < nk) cp_wait1(); else cp_wait0();
        __syncthreads();
        if (kb + 2 < nk) issue((kb + 2) % 3, kb + 2);   // stage free since last iter

        char* base = gsm + st * GSTAGE;
#pragma unroll
        for (int s = 0; s < 4; s++) {
            unsigned ah[2][4];
#pragma unroll
            for (int mt = 0; mt < 2; mt++) {
                int row = m0 + mt * 16 + (lane & 15);
                int ch  = 2 * s + (lane >> 4);
                ldmx4(ah[mt], base + row * 128 + ((ch ^ (row & 7)) << 4));
            }
#pragma unroll
            for (int ntp = 0; ntp < 4; ntp++) {
                int row = n0w + ntp * 16 + ((lane >> 4) << 3) + (lane & 7);
                int ch  = 2 * s + ((lane & 8) >> 3);
                unsigned bh4[4];
                ldmx4(bh4, base + GMAT + row * 128 + ((ch ^ (row & 7)) << 4));
                unsigned bh0[2] = { bh4[0], bh4[1] }, bh1[2] = { bh4[2], bh4[3] };
                mma16816(acc[0][2 * ntp],     ah[0], bh0);
                mma16816(acc[1][2 * ntp],     ah[1], bh0);
                mma16816(acc[0][2 * ntp + 1], ah[0], bh1);
                mma16816(acc[1][2 * ntp + 1], ah[1], bh1);
            }
        }
    }

    // ---- epilogue
    if (mode == 0) {
#pragma unroll
        for (int mt = 0; mt < 2; mt++) {
#pragma unroll
            for (int nt = 0; nt < 8; nt++) {
                int row = row0 + m0 + mt * 16 + rw;
                int col = col0 + n0w + nt * 8 + cw * 2;
                *(float2*)(C + (long)row * N + col)       = make_float2(acc[mt][nt][0], acc[mt][nt][1]);
                *(float2*)(C + (long)(row + 8) * N + col) = make_float2(acc[mt][nt][2], acc[mt][nt][3]);
            }
        }
    } else {
        const bool isv = (col0 + n0w) >= (D_ + KV_);
#pragma unroll
        for (int mt = 0; mt < 2; mt++) {
            int rbase = row0 + m0 + mt * 16 + rw;
#pragma unroll
            for (int half = 0; half < 2; half++) {
                int r = rbase + half * 8;
                int t = r & (T_ - 1);
                if (!isv) {
#pragma unroll
                    for (int nt = 0; nt < 4; nt++) {
                        float ol0[2], ol1[2];
#pragma unroll
                        for (int d = 0; d < 2; d++) {
                            int e = half * 2 + d;
                            float u1 = acc[mt][nt][e];
                            float u2 = acc[mt][nt + 4][e];
                            int i = nt * 8 + cw * 2 + d;
                            float c1 = cosb[t * HD_ + i],      s1 = sinb[t * HD_ + i];
                            float c2 = cosb[t * HD_ + i + 32], s2 = sinb[t * HD_ + i + 32];
                            ol0[d] = u1 * c1 - u2 * s1;
                            ol1[d] = u2 * c2 + u1 * s2;
                        }
                        long p = (long)r * E_ + col0 + n0w + nt * 8 + cw * 2;
                        *(unsigned*)(Ch + p)      = pack2(ol0[0], ol0[1]);
                        *(unsigned*)(Ch + p + 32) = pack2(ol1[0], ol1[1]);
                    }
                } else {
#pragma unroll
                    for (int nt = 0; nt < 8; nt++) {
                        long p = (long)r * E_ + col0 + n0w + nt * 8 + cw * 2;
                        *(unsigned*)(Ch + p) = pack2(acc[mt][nt][half * 2], acc[mt][nt][half * 2 + 1]);
                    }
                }
            }
        }
    }
}

// ---------------------------------------------------------------------------
// Flash attention (causal, GQA), mma.sync fp16. 256 threads (8 warps),
// q-tile 128 rows (16/warp). K/V loaded in 128-row stages (double-buffered
// cp.async); each stage computed as two 64-row halves with NO barrier
// between halves -> half the barrier count of 64-row stages.
// Largest-first qb scheduling.
// Smem: Q 16 KB + 2 stages x 32 KB = 80 KB -> 2 CTAs/SM.
// ---------------------------------------------------------------------------
#define AMAT_Q 16384              // 128 rows x 128 B
#define AMAT_KV 16384             // 128 rows x 128 B (K or V)
#define ASTAGE (2 * AMAT_KV)      // Kh,Vh = 32768 B
#define ATTN_SMEM (AMAT_Q + 2 * ASTAGE)   // 81920 B

__global__ void __launch_bounds__(256, 2) attn_mma(
    const __half* __restrict__ qkvh, __half* __restrict__ oh)
{
    extern __shared__ __align__(128) char asm_[];
    const int tid = threadIdx.x, lane = tid & 31, warp = tid >> 5;
    const int qb = gridDim.x - 1 - blockIdx.x;      // largest-first
    const int h = blockIdx.y, b = blockIdx.z;
    const int q0 = qb * 128;
    const int rw = lane >> 2, cw = lane & 3;
    const int wrow0 = q0 + warp * 16;

    const long qbase = (long)(b * T_) * E_ + h * HD_;
    const long kbase = (long)(b * T_) * E_ + D_ + (h >> 2) * HD_;
    const long vbase = kbase + KV_;

    // issue Q (one cp.async group): 128 rows x 8 chunks = 1024
#pragma unroll
    for (int l = 0; l < 4; l++) {
        int idx = tid + l * 256;
        int r = (idx >> 3) & 127, c = idx & 7;
        cp16(asm_ + r * 128 + ((c ^ (r & 7)) << 4),
             qkvh + qbase + (long)(q0 + r) * E_ + c * 8);
    }
    cp_commit();

    const int nb = qb + 1;      // number of 128-row KV blocks

    auto issueKV = [&](int jb, int st) {
        char* sb = asm_ + AMAT_Q + st * ASTAGE;
        const int k0 = jb * 128;
#pragma unroll
        for (int l = 0; l < 8; l++) {
            int idx = tid + l * 256;            // 0..2047
            int mat = idx >> 10;                // 0:Kh 1:Vh
            int r = (idx >> 3) & 127, c = idx & 7;
            long base = mat ? vbase : kbase;
            cp16(sb + mat * AMAT_KV + r * 128 + ((c ^ (r & 7)) << 4),
                 qkvh + base + (long)(k0 + r) * E_ + c * 8);
        }
        cp_commit();
    };

    issueKV(0, 0);
    if (nb > 1) issueKV(1, 1);

    float O[8][4];
#pragma unroll
    for (int nt = 0; nt < 8; nt++)
#pragma unroll
        for (int e = 0; e < 4; e++) O[nt][e] = 0.f;
    float m0v = -INFINITY, m1v = -INFINITY, l0v = 0.f, l1v = 0.f;

    for (int jb = 0; jb < nb; jb++) {
        const int st = jb & 1;
        if (jb + 1 < nb) cp_wait1(); else cp_wait0();
        __syncthreads();
        char* sb = asm_ + AMAT_Q + st * ASTAGE;

#pragma unroll
        for (int hb = 0; hb < 2; hb++) {
            const int k0 = jb * 128 + hb * 64;
            const int rbase = hb * 64;          // row offset within stage
            const bool active = (k0 <= wrow0 + 15) && (k0 < T_);
            if (!active) continue;

            // S = Q K^T
            float S[8][4];
#pragma unroll
            for (int nt = 0; nt < 8; nt++)
#pragma unroll
                for (int e = 0; e < 4; e++) S[nt][e] = 0.f;

#pragma unroll
            for (int s = 0; s < 4; s++) {
                unsigned qh4[4];
                {
                    int row = warp * 16 + (lane & 15);
                    int ch  = 2 * s + (lane >> 4);
                    ldmx4(qh4, asm_ + row * 128 + ((ch ^ (row & 7)) << 4));
                }
#pragma unroll
                for (int ntp = 0; ntp < 4; ntp++) {
                    int row = rbase + ntp * 16 + ((lane >> 4) << 3) + (lane & 7);
                    int ch  = 2 * s + ((lane & 8) >> 3);
                    unsigned kh4[4];
                    ldmx4(kh4, sb + row * 128 + ((ch ^ (row & 7)) << 4));
                    unsigned kh0[2] = { kh4[0], kh4[1] }, kh1[2] = { kh4[2], kh4[3] };
                    mma16816(S[2 * ntp],     qh4, kh0);
                    mma16816(S[2 * ntp + 1], qh4, kh1);
                }
            }

            const float sc = 0.125f;
            if (k0 + 63 > wrow0) {      // diagonal subtile for this warp
#pragma unroll
                for (int nt = 0; nt < 8; nt++)
#pragma unroll
                    for (int e = 0; e < 4; e++) {
                        int r = wrow0 + rw + ((e >= 2) ? 8 : 0);
                        int c = k0 + nt * 8 + cw * 2 + (e & 1);
                        S[nt][e] = (c <= r) ? S[nt][e] * sc : -1e30f;
                    }
            } else {
#pragma unroll
                for (int nt = 0; nt < 8; nt++)
#pragma unroll
                    for (int e = 0; e < 4; e++) S[nt][e] *= sc;
            }

            // online softmax
            float mx0 = -INFINITY, mx1 = -INFINITY;
#pragma unroll
            for (int nt = 0; nt < 8; nt++) {
                mx0 = fmaxf(mx0, fmaxf(S[nt][0], S[nt][1]));
                mx1 = fmaxf(mx1, fmaxf(S[nt][2], S[nt][3]));
            }
            mx0 = fmaxf(mx0, __shfl_xor_sync(0xffffffff, mx0, 1));
            mx0 = fmaxf(mx0, __shfl_xor_sync(0xffffffff, mx0, 2));
            mx1 = fmaxf(mx1, __shfl_xor_sync(0xffffffff, mx1, 1));
            mx1 = fmaxf(mx1, __shfl_xor_sync(0xffffffff, mx1, 2));
            float mn0 = fmaxf(m0v, mx0), mn1 = fmaxf(m1v, mx1);
            float a0 = exp2f((m0v - mn0) * LOG2E), a1 = exp2f((m1v - mn1) * LOG2E);
            m0v = mn0; m1v = mn1;
            float sum0 = 0.f, sum1 = 0.f;
#pragma unroll
            for (int nt = 0; nt < 8; nt++) {
                float p0 = exp2f((S[nt][0] - mn0) * LOG2E);
                float p1 = exp2f((S[nt][1] - mn0) * LOG2E);
                float p2 = exp2f((S[nt][2] - mn1) * LOG2E);
                float p3 = exp2f((S[nt][3] - mn1) * LOG2E);
                S[nt][0] = p0; S[nt][1] = p1; S[nt][2] = p2; S[nt][3] = p3;
                sum0 += p0 + p1; sum1 += p2 + p3;
            }
            sum0 += __shfl_xor_sync(0xffffffff, sum0, 1);
            sum0 += __shfl_xor_sync(0xffffffff, sum0, 2);
            sum1 += __shfl_xor_sync(0xffffffff, sum1, 1);
            sum1 += __shfl_xor_sync(0xffffffff, sum1, 2);
            l0v = l0v * a0 + sum0;
            l1v = l1v * a1 + sum1;
#pragma unroll
            for (int nt = 0; nt < 8; nt++) {
                O[nt][0] *= a0; O[nt][1] *= a0;
                O[nt][2] *= a1; O[nt][3] *= a1;
            }

            // O += P V
#pragma unroll
            for (int s = 0; s < 4; s++) {
                const int j0 = 2 * s, j1 = 2 * s + 1;
                unsigned ph_[4];
                ph_[0] = pack2(S[j0][0], S[j0][1]);
                ph_[1] = pack2(S[j0][2], S[j0][3]);
                ph_[2] = pack2(S[j1][0], S[j1][1]);
                ph_[3] = pack2(S[j1][2], S[j1][3]);
#pragma unroll
                for (int dt = 0; dt < 4; dt++) {
                    int vrow = rbase + s * 16 + (lane & 15);
                    int ch   = 2 * dt + (lane >> 4);
                    unsigned vh4[4];
                    ldmx4t(vh4, sb + AMAT_KV + vrow * 128 + ((ch ^ (vrow & 7)) << 4));
                    unsigned bh0[2] = { vh4[0], vh4[1] }, bh1[2] = { vh4[2], vh4[3] };
                    mma16816(O[2 * dt],     ph_, bh0);
                    mma16816(O[2 * dt + 1], ph_, bh1);
                }
            }
        }
        __syncthreads();
        if (jb + 2 < nb) issueKV(jb + 2, st);
    }

    // epilogue: normalize, write fp16
    float i0 = 1.f / l0v, i1 = 1.f / l1v;
    long row = (long)(b * T_ + wrow0 + rw);
    long colb = h * HD_ + cw * 2;
#pragma unroll
    for (int nt = 0; nt < 8; nt++) {
        long p0 = row * D_ + colb + nt * 8;
        long p1 = (row + 8) * D_ + colb + nt * 8;
        *(unsigned*)(oh + p0) = pack2(O[nt][0] * i0, O[nt][1] * i0);
        *(unsigned*)(oh + p1) = pack2(O[nt][2] * i1, O[nt][3] * i1);
    }
}

// ---------------------------------------------------------------------------
// Launch
// ---------------------------------------------------------------------------
extern "C" void kernel_launch(void* const* d_in, const int* in_sizes, int n_in,
                              void* d_out, int out_size)
{
    const float* x     = (const float*)d_in[0];
    const float* sinb  = (const float*)d_in[1];
    const float* cosb  = (const float*)d_in[2];
    const float* w_qkv = (const float*)d_in[3];
    const float* w_out = (const float*)d_in[4];
    float* out = (float*)d_out;

    __half *xh, *qh, *ath, *wqh, *woh;
    cudaGetSymbolAddress((void**)&xh, g_xh);
    cudaGetSymbolAddress((void**)&qh, g_qkvh);
    cudaGetSymbolAddress((void**)&ath, g_ath);
    cudaGetSymbolAddress((void**)&wqh, g_wqkv_h);
    cudaGetSymbolAddress((void**)&woh, g_wout_h);

    cudaFuncSetAttribute(gemm_fp16, cudaFuncAttributeMaxDynamicSharedMemorySize, GEMM_SMEM);
    cudaFuncSetAttribute(attn_mma, cudaFuncAttributeMaxDynamicSharedMemorySize, ATTN_SMEM);

    // 0) converts (one launch, 3 jobs)
    convert_all<<<dim3(8192, 1, 3), dim3(32, 8)>>>(x, w_qkv, w_out, xh, wqh, woh);

    // 1) QKV projection, fused RoPE -> fp16
    gemm_fp16<<<dim3(E_ / 128, BT_ / 128), 256, GEMM_SMEM>>>(
        xh, wqh, nullptr, BT_, E_, D_, 1, sinb, cosb, qh);

    // 2) Flash attention (q-tile 128, largest-first, 128-row KV stages)
    attn_mma<<<dim3(T_ / 128, NH_, B_), 256, ATTN_SMEM>>>(qh, ath);

    // 3) Output projection, fp32 epilogue
    gemm_fp16<<<dim3(D_ / 128, BT_ / 128), 256, GEMM_SMEM>>>(
        ath, woh, out, BT_, D_, D_, 0, nullptr, nullptr, nullptr);
}

// round 16
// speedup vs baseline: 1.7782x; 1.0144x over previous
#include <cuda_runtime.h>
#include <cuda_fp16.h>
#include <math.h>

// Problem constants
#define B_  2
#define T_  2048
#define D_  2048
#define E_  3072          // D + 2*KV_DIM
#define KV_ 512
#define HD_ 64
#define NH_ 32
#define BT_ 4096          // B*T

#define LOG2E 1.4426950408889634f

// Scratch (static __device__ arrays; allocation-free rule)
__device__ __half g_xh[BT_ * D_];      // x hi
__device__ __half g_qkvh[BT_ * E_];    // roped qkv hi
__device__ __half g_ath[BT_ * D_];     // attn out hi
__device__ __half g_wqkv_h[E_ * D_];   // qkv weights hi
__device__ __half g_wout_h[D_ * D_];   // out weights hi

// ---------------------------------------------------------------------------
// helpers
// ---------------------------------------------------------------------------
__device__ __forceinline__ unsigned pack2(float x, float y) {
    __half2 h = __floats2half2_rn(x, y);   // .x in low half
    return *(unsigned*)&h;
}
__device__ __forceinline__ float ex2(float x) {      // MUFU exp2 (hardware)
    float y;
    asm("ex2.approx.ftz.f32 %0, %1;" : "=f"(y) : "f"(x));
    return y;
}
__device__ __forceinline__ float frcp(float x) {     // MUFU reciprocal
    float y;
    asm("rcp.approx.ftz.f32 %0, %1;" : "=f"(y) : "f"(x));
    return y;
}
__device__ __forceinline__ void mma16816(float c[4], const unsigned a[4], const unsigned b[2]) {
    asm volatile(
        "mma.sync.aligned.m16n8k16.row.col.f32.f16.f16.f32 "
        "{%0,%1,%2,%3},{%4,%5,%6,%7},{%8,%9},{%0,%1,%2,%3};\n"
        : "+f"(c[0]), "+f"(c[1]), "+f"(c[2]), "+f"(c[3])
        : "r"(a[0]), "r"(a[1]), "r"(a[2]), "r"(a[3]), "r"(b[0]), "r"(b[1]));
}
__device__ __forceinline__ void cp16(void* dst_smem, const void* src) {
    unsigned d = (unsigned)__cvta_generic_to_shared(dst_smem);
    asm volatile("cp.async.cg.shared.global [%0], [%1], 16;\n" :: "r"(d), "l"(src));
}
__device__ __forceinline__ void cp_commit() { asm volatile("cp.async.commit_group;\n" ::: "memory"); }
__device__ __forceinline__ void cp_wait0()  { asm volatile("cp.async.wait_group 0;\n" ::: "memory"); }
__device__ __forceinline__ void cp_wait1()  { asm volatile("cp.async.wait_group 1;\n" ::: "memory"); }
__device__ __forceinline__ void ldmx4(unsigned r[4], const void* p) {
    unsigned a = (unsigned)__cvta_generic_to_shared(p);
    asm volatile("ldmatrix.sync.aligned.m8n8.x4.shared.b16 {%0,%1,%2,%3},[%4];\n"
                 : "=r"(r[0]), "=r"(r[1]), "=r"(r[2]), "=r"(r[3]) : "r"(a));
}
__device__ __forceinline__ void ldmx4t(unsigned r[4], const void* p) {
    unsigned a = (unsigned)__cvta_generic_to_shared(p);
    asm volatile("ldmatrix.sync.aligned.m8n8.x4.trans.shared.b16 {%0,%1,%2,%3},[%4];\n"
                 : "=r"(r[0]), "=r"(r[1]), "=r"(r[2]), "=r"(r[3]) : "r"(a));
}

// ---------------------------------------------------------------------------
// Merged convert kernel. One launch, three jobs (blockIdx.z):
//  z=0: x fp32 -> fp16            (8192 blocks used)
//  z=1: w_qkv transpose+convert   (6144 blocks: 96 n-tiles x 64 k-tiles)
//  z=2: w_out transpose+convert   (4096 blocks: 64 x 64)
// ---------------------------------------------------------------------------
__global__ void convert_all(const float* __restrict__ X,
                            const float* __restrict__ Wq,
                            const float* __restrict__ Wo,
                            __half* __restrict__ Xh,
                            __half* __restrict__ Oq,
                            __half* __restrict__ Oo)
{
    const int bx = blockIdx.x, z = blockIdx.z;
    if (z == 0) {
        int tid = threadIdx.y * 32 + threadIdx.x;
        long i = ((long)bx * 256 + tid) * 4;
        if (i >= (long)BT_ * D_) return;
        float4 v = *(const float4*)(X + i);
        *(uint2*)(Xh + i) = make_uint2(pack2(v.x, v.y), pack2(v.z, v.w));
        return;
    }
    const float* W = (z == 1) ? Wq : Wo;
    __half* O      = (z == 1) ? Oq : Oo;
    const int N    = (z == 1) ? E_ : D_;
    const int K    = D_;
    const int ntiles = N / 32;
    if (bx >= ntiles * (K / 32)) return;
    int n0 = (bx % ntiles) * 32, k0 = (bx / ntiles) * 32;
    __shared__ float t[32][33];
    for (int i = threadIdx.y; i < 32; i += 8)
        t[i][threadIdx.x] = W[(long)(k0 + i) * N + n0 + threadIdx.x];
    __syncthreads();
    for (int i = threadIdx.y; i < 32; i += 8)
        O[(long)(n0 + i) * K + k0 + threadIdx.x] = __float2half_rn(t[threadIdx.x][i]);
}

// ---------------------------------------------------------------------------
// GEMM (mma.sync fp16, single-term): C[M,N] = A[M,K] * W[K,N]
// A [M][K] fp16; W transposed [N][K] fp16.
// 128x128x64 tiles (BK=64), 256 threads, warptile 32x64, 128B XOR-swizzled
// rows, 3-stage cp.async ring @ 32 KB/stage -> 96 KB -> 2 CTAs/SM.
// mode 0: write C fp32.  mode 1: fused RoPE -> fp16 (QKV projection).
// ---------------------------------------------------------------------------
#define GMAT 16384                // bytes per matrix tile (128 rows x 128 B)
#define GSTAGE (2 * GMAT)         // A,B = 32768 B
#define GEMM_SMEM (3 * GSTAGE)    // 98304 B

__global__ void __launch_bounds__(256, 2) gemm_fp16(
    const __half* __restrict__ Ah_g, const __half* __restrict__ Bh_g,
    float* __restrict__ C, int M, int N, int K, int mode,
    const float* __restrict__ sinb, const float* __restrict__ cosb,
    __half* __restrict__ Ch)
{
    extern __shared__ __align__(128) char gsm[];
    const int tid = threadIdx.x, lane = tid & 31, warp = tid >> 5;
    const int row0 = blockIdx.y * 128, col0 = blockIdx.x * 128;
    const int m0 = (warp >> 1) * 32, n0w = (warp & 1) * 64;
    const int rw = lane >> 2, cw = lane & 3;
    const int nk = K >> 6;

    float acc[2][8][4];
#pragma unroll
    for (int mt = 0; mt < 2; mt++)
#pragma unroll
        for (int nt = 0; nt < 8; nt++)
#pragma unroll
            for (int e = 0; e < 4; e++) acc[mt][nt][e] = 0.f;

    auto issue = [&](int st, int kb) {
        char* base = gsm + st * GSTAGE;
#pragma unroll
        for (int l = 0; l < 8; l++) {
            int idx = tid + l * 256;               // 0..2047
            int mat = idx >> 10;                   // 0:A 1:B
            int r   = (idx >> 3) & 127;
            int c   = idx & 7;                     // logical 16B chunk
            const __half* g = mat ? Bh_g : Ah_g;
            long grow = (long)((mat ? col0 : row0) + r);
            cp16(base + mat * GMAT + r * 128 + ((c ^ (r & 7)) << 4),
                 g + grow * K + kb * 64 + c * 8);
        }
        cp_commit();
    };

    issue(0, 0);
    if (nk > 1) issue(1, 1);

    for (int kb = 0; kb < nk; kb++) {
        const int st = kb % 3;
        if (kb + 1 < nk) cp_wait1(); else cp_wait0();
        __syncthreads();
        if (kb + 2 < nk) issue((kb + 2) % 3, kb + 2);   // stage free since last iter

        char* base = gsm + st * GSTAGE;
#pragma unroll
        for (int s = 0; s < 4; s++) {
            unsigned ah[2][4];
#pragma unroll
            for (int mt = 0; mt < 2; mt++) {
                int row = m0 + mt * 16 + (lane & 15);
                int ch  = 2 * s + (lane >> 4);
                ldmx4(ah[mt], base + row * 128 + ((ch ^ (row & 7)) << 4));
            }
#pragma unroll
            for (int ntp = 0; ntp < 4; ntp++) {
                int row = n0w + ntp * 16 + ((lane >> 4) << 3) + (lane & 7);
                int ch  = 2 * s + ((lane & 8) >> 3);
                unsigned bh4[4];
                ldmx4(bh4, base + GMAT + row * 128 + ((ch ^ (row & 7)) << 4));
                unsigned bh0[2] = { bh4[0], bh4[1] }, bh1[2] = { bh4[2], bh4[3] };
                mma16816(acc[0][2 * ntp],     ah[0], bh0);
                mma16816(acc[1][2 * ntp],     ah[1], bh0);
                mma16816(acc[0][2 * ntp + 1], ah[0], bh1);
                mma16816(acc[1][2 * ntp + 1], ah[1], bh1);
            }
        }
    }

    // ---- epilogue
    if (mode == 0) {
#pragma unroll
        for (int mt = 0; mt < 2; mt++) {
#pragma unroll
            for (int nt = 0; nt < 8; nt++) {
                int row = row0 + m0 + mt * 16 + rw;
                int col = col0 + n0w + nt * 8 + cw * 2;
                *(float2*)(C + (long)row * N + col)       = make_float2(acc[mt][nt][0], acc[mt][nt][1]);
                *(float2*)(C + (long)(row + 8) * N + col) = make_float2(acc[mt][nt][2], acc[mt][nt][3]);
            }
        }
    } else {
        const bool isv = (col0 + n0w) >= (D_ + KV_);
#pragma unroll
        for (int mt = 0; mt < 2; mt++) {
            int rbase = row0 + m0 + mt * 16 + rw;
#pragma unroll
            for (int half = 0; half < 2; half++) {
                int r = rbase + half * 8;
                int t = r & (T_ - 1);
                if (!isv) {
#pragma unroll
                    for (int nt = 0; nt < 4; nt++) {
                        float ol0[2], ol1[2];
#pragma unroll
                        for (int d = 0; d < 2; d++) {
                            int e = half * 2 + d;
                            float u1 = acc[mt][nt][e];
                            float u2 = acc[mt][nt + 4][e];
                            int i = nt * 8 + cw * 2 + d;
                            float c1 = cosb[t * HD_ + i],      s1 = sinb[t * HD_ + i];
                            float c2 = cosb[t * HD_ + i + 32], s2 = sinb[t * HD_ + i + 32];
                            ol0[d] = u1 * c1 - u2 * s1;
                            ol1[d] = u2 * c2 + u1 * s2;
                        }
                        long p = (long)r * E_ + col0 + n0w + nt * 8 + cw * 2;
                        *(unsigned*)(Ch + p)      = pack2(ol0[0], ol0[1]);
                        *(unsigned*)(Ch + p + 32) = pack2(ol1[0], ol1[1]);
                    }
                } else {
#pragma unroll
                    for (int nt = 0; nt < 8; nt++) {
                        long p = (long)r * E_ + col0 + n0w + nt * 8 + cw * 2;
                        *(unsigned*)(Ch + p) = pack2(acc[mt][nt][half * 2], acc[mt][nt][half * 2 + 1]);
                    }
                }
            }
        }
    }
}

// ---------------------------------------------------------------------------
// Flash attention (causal, GQA), mma.sync fp16. 256 threads (8 warps),
// q-tile 128 rows (16/warp). K/V in 128-row double-buffered stages, two
// 64-row compute halves per stage. MUFU ex2 for softmax exponentials.
// Largest-first qb scheduling.
// Smem: Q 16 KB + 2 stages x 32 KB = 80 KB -> 2 CTAs/SM.
// ---------------------------------------------------------------------------
#define AMAT_Q 16384              // 128 rows x 128 B
#define AMAT_KV 16384             // 128 rows x 128 B (K or V)
#define ASTAGE (2 * AMAT_KV)      // Kh,Vh = 32768 B
#define ATTN_SMEM (AMAT_Q + 2 * ASTAGE)   // 81920 B

__global__ void __launch_bounds__(256, 2) attn_mma(
    const __half* __restrict__ qkvh, __half* __restrict__ oh)
{
    extern __shared__ __align__(128) char asm_[];
    const int tid = threadIdx.x, lane = tid & 31, warp = tid >> 5;
    const int qb = gridDim.x - 1 - blockIdx.x;      // largest-first
    const int h = blockIdx.y, b = blockIdx.z;
    const int q0 = qb * 128;
    const int rw = lane >> 2, cw = lane & 3;
    const int wrow0 = q0 + warp * 16;

    const long qbase = (long)(b * T_) * E_ + h * HD_;
    const long kbase = (long)(b * T_) * E_ + D_ + (h >> 2) * HD_;
    const long vbase = kbase + KV_;

    // issue Q (one cp.async group): 128 rows x 8 chunks = 1024
#pragma unroll
    for (int l = 0; l < 4; l++) {
        int idx = tid + l * 256;
        int r = (idx >> 3) & 127, c = idx & 7;
        cp16(asm_ + r * 128 + ((c ^ (r & 7)) << 4),
             qkvh + qbase + (long)(q0 + r) * E_ + c * 8);
    }
    cp_commit();

    const int nb = qb + 1;      // number of 128-row KV blocks

    auto issueKV = [&](int jb, int st) {
        char* sb = asm_ + AMAT_Q + st * ASTAGE;
        const int k0 = jb * 128;
#pragma unroll
        for (int l = 0; l < 8; l++) {
            int idx = tid + l * 256;            // 0..2047
            int mat = idx >> 10;                // 0:Kh 1:Vh
            int r = (idx >> 3) & 127, c = idx & 7;
            long base = mat ? vbase : kbase;
            cp16(sb + mat * AMAT_KV + r * 128 + ((c ^ (r & 7)) << 4),
                 qkvh + base + (long)(k0 + r) * E_ + c * 8);
        }
        cp_commit();
    };

    issueKV(0, 0);
    if (nb > 1) issueKV(1, 1);

    float O[8][4];
#pragma unroll
    for (int nt = 0; nt < 8; nt++)
#pragma unroll
        for (int e = 0; e < 4; e++) O[nt][e] = 0.f;
    float m0v = -INFINITY, m1v = -INFINITY, l0v = 0.f, l1v = 0.f;

    for (int jb = 0; jb < nb; jb++) {
        const int st = jb & 1;
        if (jb + 1 < nb) cp_wait1(); else cp_wait0();
        __syncthreads();
        char* sb = asm_ + AMAT_Q + st * ASTAGE;

#pragma unroll
        for (int hb = 0; hb < 2; hb++) {
            const int k0 = jb * 128 + hb * 64;
            const int rbase = hb * 64;          // row offset within stage
            const bool active = (k0 <= wrow0 + 15) && (k0 < T_);
            if (!active) continue;

            // S = Q K^T
            float S[8][4];
#pragma unroll
            for (int nt = 0; nt < 8; nt++)
#pragma unroll
                for (int e = 0; e < 4; e++) S[nt][e] = 0.f;

#pragma unroll
            for (int s = 0; s < 4; s++) {
                unsigned qh4[4];
                {
                    int row = warp * 16 + (lane & 15);
                    int ch  = 2 * s + (lane >> 4);
                    ldmx4(qh4, asm_ + row * 128 + ((ch ^ (row & 7)) << 4));
                }
#pragma unroll
                for (int ntp = 0; ntp < 4; ntp++) {
                    int row = rbase + ntp * 16 + ((lane >> 4) << 3) + (lane & 7);
                    int ch  = 2 * s + ((lane & 8) >> 3);
                    unsigned kh4[4];
                    ldmx4(kh4, sb + row * 128 + ((ch ^ (row & 7)) << 4));
                    unsigned kh0[2] = { kh4[0], kh4[1] }, kh1[2] = { kh4[2], kh4[3] };
                    mma16816(S[2 * ntp],     qh4, kh0);
                    mma16816(S[2 * ntp + 1], qh4, kh1);
                }
            }

            const float sc = 0.125f;
            if (k0 + 63 > wrow0) {      // diagonal subtile for this warp
#pragma unroll
                for (int nt = 0; nt < 8; nt++)
#pragma unroll
                    for (int e = 0; e < 4; e++) {
                        int r = wrow0 + rw + ((e >= 2) ? 8 : 0);
                        int c = k0 + nt * 8 + cw * 2 + (e & 1);
                        S[nt][e] = (c <= r) ? S[nt][e] * sc : -1e30f;
                    }
            } else {
#pragma unroll
                for (int nt = 0; nt < 8; nt++)
#pragma unroll
                    for (int e = 0; e < 4; e++) S[nt][e] *= sc;
            }

            // online softmax (MUFU ex2)
            float mx0 = -INFINITY, mx1 = -INFINITY;
#pragma unroll
            for (int nt = 0; nt < 8; nt++) {
                mx0 = fmaxf(mx0, fmaxf(S[nt][0], S[nt][1]));
                mx1 = fmaxf(mx1, fmaxf(S[nt][2], S[nt][3]));
            }
            mx0 = fmaxf(mx0, __shfl_xor_sync(0xffffffff, mx0, 1));
            mx0 = fmaxf(mx0, __shfl_xor_sync(0xffffffff, mx0, 2));
            mx1 = fmaxf(mx1, __shfl_xor_sync(0xffffffff, mx1, 1));
            mx1 = fmaxf(mx1, __shfl_xor_sync(0xffffffff, mx1, 2));
            float mn0 = fmaxf(m0v, mx0), mn1 = fmaxf(m1v, mx1);
            float a0 = ex2((m0v - mn0) * LOG2E), a1 = ex2((m1v - mn1) * LOG2E);
            m0v = mn0; m1v = mn1;
            float sum0 = 0.f, sum1 = 0.f;
#pragma unroll
            for (int nt = 0; nt < 8; nt++) {
                float p0 = ex2((S[nt][0] - mn0) * LOG2E);
                float p1 = ex2((S[nt][1] - mn0) * LOG2E);
                float p2 = ex2((S[nt][2] - mn1) * LOG2E);
                float p3 = ex2((S[nt][3] - mn1) * LOG2E);
                S[nt][0] = p0; S[nt][1] = p1; S[nt][2] = p2; S[nt][3] = p3;
                sum0 += p0 + p1; sum1 += p2 + p3;
            }
            sum0 += __shfl_xor_sync(0xffffffff, sum0, 1);
            sum0 += __shfl_xor_sync(0xffffffff, sum0, 2);
            sum1 += __shfl_xor_sync(0xffffffff, sum1, 1);
            sum1 += __shfl_xor_sync(0xffffffff, sum1, 2);
            l0v = l0v * a0 + sum0;
            l1v = l1v * a1 + sum1;
#pragma unroll
            for (int nt = 0; nt < 8; nt++) {
                O[nt][0] *= a0; O[nt][1] *= a0;
                O[nt][2] *= a1; O[nt][3] *= a1;
            }

            // O += P V
#pragma unroll
            for (int s = 0; s < 4; s++) {
                const int j0 = 2 * s, j1 = 2 * s + 1;
                unsigned ph_[4];
                ph_[0] = pack2(S[j0][0], S[j0][1]);
                ph_[1] = pack2(S[j0][2], S[j0][3]);
                ph_[2] = pack2(S[j1][0], S[j1][1]);
                ph_[3] = pack2(S[j1][2], S[j1][3]);
#pragma unroll
                for (int dt = 0; dt < 4; dt++) {
                    int vrow = rbase + s * 16 + (lane & 15);
                    int ch   = 2 * dt + (lane >> 4);
                    unsigned vh4[4];
                    ldmx4t(vh4, sb + AMAT_KV + vrow * 128 + ((ch ^ (vrow & 7)) << 4));
                    unsigned bh0[2] = { vh4[0], vh4[1] }, bh1[2] = { vh4[2], vh4[3] };
                    mma16816(O[2 * dt],     ph_, bh0);
                    mma16816(O[2 * dt + 1], ph_, bh1);
                }
            }
        }
        __syncthreads();
        if (jb + 2 < nb) issueKV(jb + 2, st);
    }

    // epilogue: normalize (MUFU rcp), write fp16
    float i0 = frcp(l0v), i1 = frcp(l1v);
    long row = (long)(b * T_ + wrow0 + rw);
    long colb = h * HD_ + cw * 2;
#pragma unroll
    for (int nt = 0; nt < 8; nt++) {
        long p0 = row * D_ + colb + nt * 8;
        long p1 = (row + 8) * D_ + colb + nt * 8;
        *(unsigned*)(oh + p0) = pack2(O[nt][0] * i0, O[nt][1] * i0);
        *(unsigned*)(oh + p1) = pack2(O[nt][2] * i1, O[nt][3] * i1);
    }
}

// ---------------------------------------------------------------------------
// Launch
// ---------------------------------------------------------------------------
extern "C" void kernel_launch(void* const* d_in, const int* in_sizes, int n_in,
                              void* d_out, int out_size)
{
    const float* x     = (const float*)d_in[0];
    const float* sinb  = (const float*)d_in[1];
    const float* cosb  = (const float*)d_in[2];
    const float* w_qkv = (const float*)d_in[3];
    const float* w_out = (const float*)d_in[4];
    float* out = (float*)d_out;

    __half *xh, *qh, *ath, *wqh, *woh;
    cudaGetSymbolAddress((void**)&xh, g_xh);
    cudaGetSymbolAddress((void**)&qh, g_qkvh);
    cudaGetSymbolAddress((void**)&ath, g_ath);
    cudaGetSymbolAddress((void**)&wqh, g_wqkv_h);
    cudaGetSymbolAddress((void**)&woh, g_wout_h);

    cudaFuncSetAttribute(gemm_fp16, cudaFuncAttributeMaxDynamicSharedMemorySize, GEMM_SMEM);
    cudaFuncSetAttribute(attn_mma, cudaFuncAttributeMaxDynamicSharedMemorySize, ATTN_SMEM);

    // 0) converts (one launch, 3 jobs)
    convert_all<<<dim3(8192, 1, 3), dim3(32, 8)>>>(x, w_qkv, w_out, xh, wqh, woh);

    // 1) QKV projection, fused RoPE -> fp16
    gemm_fp16<<<dim3(E_ / 128, BT_ / 128), 256, GEMM_SMEM>>>(
        xh, wqh, nullptr, BT_, E_, D_, 1, sinb, cosb, qh);

    // 2) Flash attention (q-tile 128, largest-first, 128-row KV stages)
    attn_mma<<<dim3(T_ / 128, NH_, B_), 256, ATTN_SMEM>>>(qh, ath);

    // 3) Output projection, fp32 epilogue
    gemm_fp16<<<dim3(D_ / 128, BT_ / 128), 256, GEMM_SMEM>>>(
        ath, woh, out, BT_, D_, D_, 0, nullptr, nullptr, nullptr);
}